// round 7
// baseline (speedup 1.0000x reference)
#include <cuda_runtime.h>
#include <cuda_bf16.h>
#include <cstdint>
#include <math.h>

#define B_SZ   4
#define S_LEN  2048
#define NH     16
#define HD     128
#define DM     2048
#define M_TOT  (B_SZ * S_LEN)
typedef __nv_bfloat16 bf;

// ---------------- scratch (device globals; allocation-free) ----------------
__device__ __align__(128) bf      g_xh [(size_t)M_TOT * DM];
__device__ __align__(128) uint8_t g_xqh[(size_t)M_TOT * DM];
__device__ __align__(128) uint8_t g_xql[(size_t)M_TOT * DM];
__device__ __align__(128) float   g_qf [(size_t)M_TOT * DM];
__device__ __align__(128) float   g_kf [(size_t)M_TOT * DM];
__device__ __align__(128) bf      g_qh [(size_t)M_TOT * DM];
__device__ __align__(128) bf      g_ql [(size_t)M_TOT * DM];
__device__ __align__(128) bf      g_kh [(size_t)M_TOT * DM];
__device__ __align__(128) bf      g_kl [(size_t)M_TOT * DM];
__device__ __align__(128) bf      g_vh [(size_t)M_TOT * DM];
__device__ __align__(128) bf      g_vl [(size_t)M_TOT * DM];
__device__ __align__(128) bf      g_ah [(size_t)M_TOT * DM];
__device__ __align__(128) uint8_t g_aqh[(size_t)M_TOT * DM];
__device__ __align__(128) uint8_t g_aql[(size_t)M_TOT * DM];
__device__ __align__(128) bf      g_wh [4][(size_t)DM * DM];
__device__ __align__(128) uint8_t g_wqh[4][(size_t)DM * DM];
__device__ __align__(128) uint8_t g_wql[4][(size_t)DM * DM];

// ---------------- helpers ----------------
__device__ __forceinline__ uint32_t smem_u32(const void* p) {
    uint32_t a;
    asm("{ .reg .u64 t; cvta.to.shared.u64 t, %1; cvt.u32.u64 %0, t; }"
        : "=r"(a) : "l"(p));
    return a;
}
__device__ __forceinline__ uint32_t pack_bf2(bf a, bf b) {
    __nv_bfloat162 t = __halves2bfloat162(a, b);
    return *reinterpret_cast<uint32_t*>(&t);
}
__device__ __forceinline__ void split1(float v, bf& h, bf& l) {
    h = __float2bfloat16(v);
    l = __float2bfloat16(v - __bfloat162float(h));
}
// byte0 = e4m3(a), byte1 = e4m3(b)
__device__ __forceinline__ uint16_t fp8x2(float a, float b) {
    uint16_t r;
    asm("cvt.rn.satfinite.e4m3x2.f32 %0, %1, %2;" : "=h"(r) : "f"(b), "f"(a));
    return r;
}

#define MMA2(d, a0, a1, a2, a3, b0, b1)                                      \
    asm volatile(                                                            \
        "mma.sync.aligned.m16n8k16.row.col.f32.bf16.bf16.f32 "               \
        "{%0,%1,%2,%3}, {%4,%5,%6,%7}, {%8,%9}, {%0,%1,%2,%3};"              \
        : "+f"((d)[0]), "+f"((d)[1]), "+f"((d)[2]), "+f"((d)[3])             \
        : "r"(a0), "r"(a1), "r"(a2), "r"(a3), "r"(b0), "r"(b1))

#define MMAF8(d, a0, a1, a2, a3, b0, b1)                                     \
    asm volatile(                                                            \
        "mma.sync.aligned.m16n8k32.row.col.f32.e4m3.e4m3.f32 "               \
        "{%0,%1,%2,%3}, {%4,%5,%6,%7}, {%8,%9}, {%0,%1,%2,%3};"              \
        : "+f"((d)[0]), "+f"((d)[1]), "+f"((d)[2]), "+f"((d)[3])             \
        : "r"(a0), "r"(a1), "r"(a2), "r"(a3), "r"(b0), "r"(b1))

#define LDMX4(r0, r1, r2, r3, addr)                                          \
    asm volatile("ldmatrix.sync.aligned.m8n8.x4.shared.b16 "                 \
        "{%0,%1,%2,%3}, [%4];"                                               \
        : "=r"(r0), "=r"(r1), "=r"(r2), "=r"(r3) : "r"(addr))

#define LDMX4T(r0, r1, r2, r3, addr)                                         \
    asm volatile("ldmatrix.sync.aligned.m8n8.x4.trans.shared.b16 "           \
        "{%0,%1,%2,%3}, [%4];"                                               \
        : "=r"(r0), "=r"(r1), "=r"(r2), "=r"(r3) : "r"(addr))

#define CP16(dst, src)                                                       \
    asm volatile("cp.async.cg.shared.global [%0], [%1], 16;"                 \
                 :: "r"(dst), "l"(src))
#define CP_COMMIT() asm volatile("cp.async.commit_group;" ::)
#define CP_WAIT(n)  asm volatile("cp.async.wait_group %0;" :: "n"(n))

// ---------------------------------------------------------------------------
// x: fp32 -> bf16 hi + fp8(x/4) + fp8(lo*256)
// ---------------------------------------------------------------------------
__global__ __launch_bounds__(256) void convert_split_x(
    const float* __restrict__ in, bf* __restrict__ H,
    uint8_t* __restrict__ QH, uint8_t* __restrict__ QL)
{
    size_t base = ((size_t)blockIdx.x * 256 + threadIdx.x) * 8;
    float v[8], l[8]; bf h[8];
    *(float4*)(v)     = *(const float4*)(in + base);
    *(float4*)(v + 4) = *(const float4*)(in + base + 4);
    #pragma unroll
    for (int i = 0; i < 8; i++) {
        h[i] = __float2bfloat16(v[i]);
        l[i] = v[i] - __bfloat162float(h[i]);
    }
    uint4 hv;
    hv.x = pack_bf2(h[0], h[1]); hv.y = pack_bf2(h[2], h[3]);
    hv.z = pack_bf2(h[4], h[5]); hv.w = pack_bf2(h[6], h[7]);
    *(uint4*)(H + base) = hv;
    uint2 qh, ql;
    qh.x = (uint32_t)fp8x2(v[0]*0.25f, v[1]*0.25f) | ((uint32_t)fp8x2(v[2]*0.25f, v[3]*0.25f) << 16);
    qh.y = (uint32_t)fp8x2(v[4]*0.25f, v[5]*0.25f) | ((uint32_t)fp8x2(v[6]*0.25f, v[7]*0.25f) << 16);
    ql.x = (uint32_t)fp8x2(l[0]*256.f, l[1]*256.f) | ((uint32_t)fp8x2(l[2]*256.f, l[3]*256.f) << 16);
    ql.y = (uint32_t)fp8x2(l[4]*256.f, l[5]*256.f) | ((uint32_t)fp8x2(l[6]*256.f, l[7]*256.f) << 16);
    *(uint2*)(QH + base) = qh;
    *(uint2*)(QL + base) = ql;
}

// ---------------------------------------------------------------------------
// w [K,N] fp32 -> [N,K]: bf16 hi + fp8(w*8) + fp8(lo*8192)
// ---------------------------------------------------------------------------
__global__ __launch_bounds__(256) void transpose_convert(
    const float* __restrict__ in, bf* __restrict__ H,
    uint8_t* __restrict__ QH, uint8_t* __restrict__ QL)
{
    __shared__ float t[32][33];
    int x = blockIdx.x * 32 + threadIdx.x;
    int y = blockIdx.y * 32 + threadIdx.y;
    #pragma unroll
    for (int i = 0; i < 4; i++)
        t[threadIdx.y + i * 8][threadIdx.x] = in[(size_t)(y + i * 8) * DM + x];
    __syncthreads();
    x = blockIdx.y * 32 + threadIdx.x;
    y = blockIdx.x * 32 + threadIdx.y;
    #pragma unroll
    for (int i = 0; i < 4; i++) {
        float v = t[threadIdx.x][threadIdx.y + i * 8];
        bf h = __float2bfloat16(v);
        float l = v - __bfloat162float(h);
        size_t o = (size_t)(y + i * 8) * DM + x;
        H[o]  = h;
        QH[o] = (uint8_t)(fp8x2(v * 8.0f, 0.f) & 0xFF);
        QL[o] = (uint8_t)(fp8x2(l * 8192.0f, 0.f) & 0xFF);
    }
}

// ---------------------------------------------------------------------------
// GEMM v3: C = A*B^T. hi*hi bf16 (k16); (a*w_lo + a_lo*w) in e4m3 (k32)
// at scale 2^11. 128x128 tile, 512 thr (16 warps m32n32), 3-stage cp.async.
// ---------------------------------------------------------------------------
#define SA_H   0u
#define SA_QH  10240u
#define SA_QL  16384u
#define SB_H   22528u
#define SB_QH  32768u
#define SB_QL  38912u
#define G_STAGE 45056u
#define GEMM3_SMEM (3 * 45056)

template<int EPI>
__global__ __launch_bounds__(512, 1) void gemm_f8c(
    const bf* __restrict__ Ah, const uint8_t* __restrict__ Aqh,
    const uint8_t* __restrict__ Aql,
    const bf* __restrict__ Bh, const uint8_t* __restrict__ Bqh,
    const uint8_t* __restrict__ Bql,
    float* __restrict__ C, bf* __restrict__ Ch, bf* __restrict__ Cl,
    int M, int N, int K)
{
    extern __shared__ __align__(16) char gsm[];
    const uint32_t sb = smem_u32(gsm);

    const int tid  = threadIdx.x;
    const int lane = tid & 31;
    const int wid  = tid >> 5;
    const int wm   = wid & 3;
    const int wn   = wid >> 2;
    const int n0 = blockIdx.x * 128;
    const int m0 = blockIdx.y * 128;

    const int lr = tid >> 2, lc = tid & 3;            // bf16 loaders
    const int qr = (tid & 255) >> 1, qc = tid & 1;    // fp8 loaders
    const bool loH = tid < 256;

    const int lm = lane & 15, lh = lane >> 4;
    const int kb_row   = (lane >> 4) * 8 + (lane & 7);
    const int kb_chalf = (lane >> 3) & 1;

    float acc[2][4][4], accc[2][4][4];
    #pragma unroll
    for (int mt = 0; mt < 2; mt++)
        #pragma unroll
        for (int nt = 0; nt < 4; nt++)
            #pragma unroll
            for (int e = 0; e < 4; e++) { acc[mt][nt][e] = 0.f; accc[mt][nt][e] = 0.f; }

    const int NK = K / 32;

    auto issue = [&](int kt) {
        const uint32_t s = sb + (uint32_t)(kt % 3) * G_STAGE;
        CP16(s + SA_H + lr * 80 + lc * 16, Ah + (size_t)(m0 + lr) * K + kt * 32 + lc * 8);
        CP16(s + SB_H + lr * 80 + lc * 16, Bh + (size_t)(n0 + lr) * K + kt * 32 + lc * 8);
        if (loH) {
            CP16(s + SA_QH + qr * 48 + qc * 16, Aqh + (size_t)(m0 + qr) * K + kt * 32 + qc * 16);
            CP16(s + SB_QH + qr * 48 + qc * 16, Bqh + (size_t)(n0 + qr) * K + kt * 32 + qc * 16);
        } else {
            CP16(s + SA_QL + qr * 48 + qc * 16, Aql + (size_t)(m0 + qr) * K + kt * 32 + qc * 16);
            CP16(s + SB_QL + qr * 48 + qc * 16, Bql + (size_t)(n0 + qr) * K + kt * 32 + qc * 16);
        }
        CP_COMMIT();
    };

    issue(0);
    issue(1);

    for (int kt = 0; kt < NK; kt++) {
        if (kt + 1 < NK) CP_WAIT(1); else CP_WAIT(0);
        __syncthreads();
        if (kt + 2 < NK) issue(kt + 2);

        const uint32_t s = sb + (uint32_t)(kt % 3) * G_STAGE;

        // ---- fp8 corrections (k=32 in one MMA) ----
        uint32_t aqh[2][4], aql[2][4], bqh[2][4], bql[2][4];
        #pragma unroll
        for (int mt = 0; mt < 2; mt++) {
            uint32_t aaddr = s + SA_QH + (uint32_t)(wm * 32 + mt * 16 + lm) * 48 + lh * 16;
            LDMX4(aqh[mt][0], aqh[mt][1], aqh[mt][2], aqh[mt][3], aaddr);
            LDMX4(aql[mt][0], aql[mt][1], aql[mt][2], aql[mt][3], aaddr + (SA_QL - SA_QH));
        }
        #pragma unroll
        for (int ng = 0; ng < 2; ng++) {
            uint32_t baddr = s + SB_QH + (uint32_t)(wn * 32 + ng * 16 + kb_row) * 48 + kb_chalf * 16;
            LDMX4(bqh[ng][0], bqh[ng][1], bqh[ng][2], bqh[ng][3], baddr);
            LDMX4(bql[ng][0], bql[ng][1], bql[ng][2], bql[ng][3], baddr + (SB_QL - SB_QH));
        }
        #pragma unroll
        for (int mt = 0; mt < 2; mt++)
            #pragma unroll
            for (int nt = 0; nt < 4; nt++) {
                const int ng = nt >> 1, o = (nt & 1) * 2;
                MMAF8(accc[mt][nt], aqh[mt][0], aqh[mt][1], aqh[mt][2], aqh[mt][3],
                      bql[ng][o], bql[ng][o + 1]);
                MMAF8(accc[mt][nt], aql[mt][0], aql[mt][1], aql[mt][2], aql[mt][3],
                      bqh[ng][o], bqh[ng][o + 1]);
            }

        // ---- bf16 hi*hi (2 k16 steps) ----
        #pragma unroll
        for (int kc = 0; kc < 2; kc++) {
            uint32_t ah[2][4], bh[2][4];
            #pragma unroll
            for (int mt = 0; mt < 2; mt++) {
                uint32_t aaddr = s + SA_H +
                    (uint32_t)(wm * 32 + mt * 16 + lm) * 80 + kc * 32 + lh * 16;
                LDMX4(ah[mt][0], ah[mt][1], ah[mt][2], ah[mt][3], aaddr);
            }
            #pragma unroll
            for (int ng = 0; ng < 2; ng++) {
                uint32_t baddr = s + SB_H +
                    (uint32_t)(wn * 32 + ng * 16 + kb_row) * 80 + kc * 32 + kb_chalf * 16;
                LDMX4(bh[ng][0], bh[ng][1], bh[ng][2], bh[ng][3], baddr);
            }
            #pragma unroll
            for (int mt = 0; mt < 2; mt++)
                #pragma unroll
                for (int nt = 0; nt < 4; nt++) {
                    const int ng = nt >> 1, o = (nt & 1) * 2;
                    MMA2(acc[mt][nt], ah[mt][0], ah[mt][1], ah[mt][2], ah[mt][3],
                         bh[ng][o], bh[ng][o + 1]);
                }
        }
        __syncthreads();
    }

    const int mrow = lane >> 2;
    const int kcol = (lane & 3) * 2;
    const float ICS = 1.0f / 2048.0f;
    #pragma unroll
    for (int mt = 0; mt < 2; mt++) {
        #pragma unroll
        for (int nt = 0; nt < 4; nt++) {
            int row = m0 + wm * 32 + mt * 16 + mrow;
            int col = n0 + wn * 32 + nt * 8 + kcol;
            float v0 = acc[mt][nt][0] + accc[mt][nt][0] * ICS;
            float v1 = acc[mt][nt][1] + accc[mt][nt][1] * ICS;
            float v2 = acc[mt][nt][2] + accc[mt][nt][2] * ICS;
            float v3 = acc[mt][nt][3] + accc[mt][nt][3] * ICS;
            if (EPI == 0) {
                *(float2*)(C + (size_t)row * N + col)       = make_float2(v0, v1);
                *(float2*)(C + (size_t)(row + 8) * N + col) = make_float2(v2, v3);
            } else {
                bf h0, l0, h1, l1;
                split1(v0, h0, l0); split1(v1, h1, l1);
                *(uint32_t*)(Ch + (size_t)row * N + col) = pack_bf2(h0, h1);
                *(uint32_t*)(Cl + (size_t)row * N + col) = pack_bf2(l0, l1);
                split1(v2, h0, l0); split1(v3, h1, l1);
                *(uint32_t*)(Ch + (size_t)(row + 8) * N + col) = pack_bf2(h0, h1);
                *(uint32_t*)(Cl + (size_t)(row + 8) * N + col) = pack_bf2(l0, l1);
            }
        }
    }
}

// ---------------------------------------------------------------------------
// RoPE on fp32 q,k -> split bf16; q scaled by 1/sqrt(H).
// ---------------------------------------------------------------------------
__global__ void rope_convert(
    const float* __restrict__ q, const float* __restrict__ k,
    bf* __restrict__ qh, bf* __restrict__ ql,
    bf* __restrict__ kh, bf* __restrict__ kl, int total)
{
    int idx = blockIdx.x * blockDim.x + threadIdx.x;
    if (idx >= total) return;
    int pair = idx & 63;
    int m    = idx >> 10;
    int s    = m & (S_LEN - 1);

    float fraction  = (2.0f * (float)pair) / (float)HD;
    float timescale = exp2f(fraction * 13.287712379549449f);
    float ang = (float)s / timescale;
    float sv, cv;
    sincosf(ang, &sv, &cv);

    size_t base = (size_t)m * DM + (size_t)((idx >> 6) & (NH - 1)) * HD + pair * 2;
    const float qs = 0.08838834764831845f;

    float q1 = q[base], q2 = q[base + 1];
    float r1 = (q1 * cv - q2 * sv) * qs;
    float r2 = (q2 * cv + q1 * sv) * qs;
    bf h1, l1, h2, l2;
    split1(r1, h1, l1); split1(r2, h2, l2);
    *(uint32_t*)(qh + base) = pack_bf2(h1, h2);
    *(uint32_t*)(ql + base) = pack_bf2(l1, l2);

    float k1 = k[base], k2 = k[base + 1];
    r1 = k1 * cv - k2 * sv;
    r2 = k2 * cv + k1 * sv;
    split1(r1, h1, l1); split1(r2, h2, l2);
    *(uint32_t*)(kh + base) = pack_bf2(h1, h2);
    *(uint32_t*)(kl + base) = pack_bf2(l1, l2);
}

// ---------------------------------------------------------------------------
// Flash attention (R5 design); epilogue also emits fp8 attn operands.
// ---------------------------------------------------------------------------
#define FSTR    136
#define F_QH    0
#define F_QL    (128 * FSTR)
#define F_KV0   (2 * 128 * FSTR)
#define F_KVSZ  (4 * 64 * FSTR)
#define LO_OFF  (64 * FSTR)
#define FLASH_SMEM_BYTES ((F_KV0 + 2 * F_KVSZ) * 2)

__global__ __launch_bounds__(256, 1) void flash_tc2(
    const bf* __restrict__ Qh, const bf* __restrict__ Ql,
    const bf* __restrict__ Kh, const bf* __restrict__ Kl,
    const bf* __restrict__ Vh, const bf* __restrict__ Vl,
    bf* __restrict__ Oh, uint8_t* __restrict__ Oqh, uint8_t* __restrict__ Oql)
{
    extern __shared__ __align__(16) bf fsm[];
    const uint32_t sb = smem_u32(fsm);

    const int tid  = threadIdx.x;
    const int lane = tid & 31;
    const int w    = tid >> 5;
    const int qt   = blockIdx.x;
    const int hN   = blockIdx.y;
    const int b    = blockIdx.z;
    const int q0   = qt * 128;
    const size_t head = (size_t)hN * HD;

    auto issue_kv = [&](int kt, int st) {
        const int k0 = kt * 64;
        const uint32_t base = sb + (F_KV0 + st * F_KVSZ) * 2;
        #pragma unroll
        for (int i = 0; i < 4; i++) {
            int idx = tid + i * 256;
            int row = idx >> 4, ch = idx & 15;
            uint32_t doff = (uint32_t)(row * FSTR + ch * 8) * 2;
            size_t g = ((size_t)(b * S_LEN + k0 + row)) * DM + head + ch * 8;
            CP16(base + doff,                  Kh + g);
            CP16(base + LO_OFF * 2 + doff,     Kl + g);
            CP16(base + 2 * LO_OFF * 2 + doff, Vh + g);
            CP16(base + 3 * LO_OFF * 2 + doff, Vl + g);
        }
        CP_COMMIT();
    };

    #pragma unroll
    for (int i = 0; i < 8; i++) {
        int idx = tid + i * 256;
        int row = idx >> 4, ch = idx & 15;
        uint32_t doff = (uint32_t)(row * FSTR + ch * 8) * 2;
        size_t g = ((size_t)(b * S_LEN + q0 + row)) * DM + head + ch * 8;
        CP16(sb + doff,            Qh + g);
        CP16(sb + F_QL * 2 + doff, Ql + g);
    }
    issue_kv(0, 0);

    float m0 = -1e30f, m1 = -1e30f, l0 = 0.f, l1 = 0.f;
    float o[16][4];
    #pragma unroll
    for (int t = 0; t < 16; t++)
        #pragma unroll
        for (int e = 0; e < 4; e++) o[t][e] = 0.f;

    const int ktiles = 2 * qt + 2;

    const uint32_t qa_base =
        sb + ((w * 16 + (lane & 15)) * FSTR + (lane >> 4) * 8) * 2;
    const uint32_t kb_row    = (lane >> 4) * 8 + (lane & 7);
    const uint32_t kb_coladd = ((lane >> 3) & 1) * 8;
    const uint32_t vb_rowadd = ((lane >> 3) & 1) * 8 + (lane & 7);
    const uint32_t vb_coladd = (lane >> 4) * 8;

    for (int kt = 0; kt < ktiles; kt++) {
        const int st = kt & 1;
        if (kt + 1 < ktiles) { issue_kv(kt + 1, st ^ 1); CP_WAIT(1); }
        else                 { CP_WAIT(0); }
        __syncthreads();

        const uint32_t khb = F_KV0 + st * F_KVSZ;
        const uint32_t vhb = khb + 2 * LO_OFF;

        float c[8][4];
        #pragma unroll
        for (int t = 0; t < 8; t++)
            #pragma unroll
            for (int e = 0; e < 4; e++) c[t][e] = 0.f;

        #pragma unroll
        for (int kc = 0; kc < 8; kc++) {
            uint32_t ah0, ah1, ah2, ah3, al0, al1, al2, al3;
            uint32_t qaddr = qa_base + kc * 32;
            LDMX4(ah0, ah1, ah2, ah3, qaddr);
            LDMX4(al0, al1, al2, al3, qaddr + F_QL * 2);
            #pragma unroll
            for (int tp = 0; tp < 4; tp++) {
                uint32_t bh0, bh1, bh2, bh3, bl0, bl1, bl2, bl3;
                uint32_t kaddr = sb +
                    (khb + (tp * 16 + kb_row) * FSTR + kc * 16 + kb_coladd) * 2;
                LDMX4(bh0, bh1, bh2, bh3, kaddr);
                LDMX4(bl0, bl1, bl2, bl3, kaddr + LO_OFF * 2);
                MMA2(c[2*tp],   ah0, ah1, ah2, ah3, bh0, bh1);
                MMA2(c[2*tp],   ah0, ah1, ah2, ah3, bl0, bl1);
                MMA2(c[2*tp],   al0, al1, al2, al3, bh0, bh1);
                MMA2(c[2*tp+1], ah0, ah1, ah2, ah3, bh2, bh3);
                MMA2(c[2*tp+1], ah0, ah1, ah2, ah3, bl2, bl3);
                MMA2(c[2*tp+1], al0, al1, al2, al3, bh2, bh3);
            }
        }

        const int rowg0 = q0 + w * 16 + (lane >> 2);
        if (kt >= 2 * qt) {
            const int k0 = kt * 64;
            #pragma unroll
            for (int t = 0; t < 8; t++) {
                int colb = k0 + t * 8 + (lane & 3) * 2;
                if (colb     > rowg0)     c[t][0] = -1e30f;
                if (colb + 1 > rowg0)     c[t][1] = -1e30f;
                if (colb     > rowg0 + 8) c[t][2] = -1e30f;
                if (colb + 1 > rowg0 + 8) c[t][3] = -1e30f;
            }
        }

        float mx0 = -1e30f, mx1 = -1e30f;
        #pragma unroll
        for (int t = 0; t < 8; t++) {
            mx0 = fmaxf(mx0, fmaxf(c[t][0], c[t][1]));
            mx1 = fmaxf(mx1, fmaxf(c[t][2], c[t][3]));
        }
        mx0 = fmaxf(mx0, __shfl_xor_sync(0xffffffffu, mx0, 1));
        mx0 = fmaxf(mx0, __shfl_xor_sync(0xffffffffu, mx0, 2));
        mx1 = fmaxf(mx1, __shfl_xor_sync(0xffffffffu, mx1, 1));
        mx1 = fmaxf(mx1, __shfl_xor_sync(0xffffffffu, mx1, 2));
        const float mn0 = fmaxf(m0, mx0);
        const float mn1 = fmaxf(m1, mx1);
        const float sc0 = __expf(m0 - mn0);
        const float sc1 = __expf(m1 - mn1);
        float sum0 = 0.f, sum1 = 0.f;
        #pragma unroll
        for (int t = 0; t < 8; t++) {
            c[t][0] = __expf(c[t][0] - mn0); sum0 += c[t][0];
            c[t][1] = __expf(c[t][1] - mn0); sum0 += c[t][1];
            c[t][2] = __expf(c[t][2] - mn1); sum1 += c[t][2];
            c[t][3] = __expf(c[t][3] - mn1); sum1 += c[t][3];
        }
        sum0 += __shfl_xor_sync(0xffffffffu, sum0, 1);
        sum0 += __shfl_xor_sync(0xffffffffu, sum0, 2);
        sum1 += __shfl_xor_sync(0xffffffffu, sum1, 1);
        sum1 += __shfl_xor_sync(0xffffffffu, sum1, 2);
        m0 = mn0; m1 = mn1;
        l0 = l0 * sc0 + sum0;
        l1 = l1 * sc1 + sum1;
        #pragma unroll
        for (int t = 0; t < 16; t++) {
            o[t][0] *= sc0; o[t][1] *= sc0;
            o[t][2] *= sc1; o[t][3] *= sc1;
        }

        #pragma unroll
        for (int kc = 0; kc < 4; kc++) {
            uint32_t pah[4], pal[4];
            #pragma unroll
            for (int half = 0; half < 2; half++) {
                const int t = 2 * kc + half;
                bf h0, l0b, h1, l1b, h2, l2b, h3, l3b;
                split1(c[t][0], h0, l0b); split1(c[t][1], h1, l1b);
                split1(c[t][2], h2, l2b); split1(c[t][3], h3, l3b);
                pah[2*half]   = pack_bf2(h0, h1);
                pah[2*half+1] = pack_bf2(h2, h3);
                pal[2*half]   = pack_bf2(l0b, l1b);
                pal[2*half+1] = pack_bf2(l2b, l3b);
            }
            #pragma unroll
            for (int tp = 0; tp < 8; tp++) {
                uint32_t vh0, vh1, vh2, vh3, vl0, vl1, vl2, vl3;
                uint32_t vaddr = sb +
                    (vhb + (kc * 16 + vb_rowadd) * FSTR + tp * 16 + vb_coladd) * 2;
                LDMX4T(vh0, vh1, vh2, vh3, vaddr);
                LDMX4T(vl0, vl1, vl2, vl3, vaddr + LO_OFF * 2);
                MMA2(o[2*tp],   pah[0], pah[1], pah[2], pah[3], vh0, vh1);
                MMA2(o[2*tp],   pah[0], pah[1], pah[2], pah[3], vl0, vl1);
                MMA2(o[2*tp],   pal[0], pal[1], pal[2], pal[3], vh0, vh1);
                MMA2(o[2*tp+1], pah[0], pah[1], pah[2], pah[3], vh2, vh3);
                MMA2(o[2*tp+1], pah[0], pah[1], pah[2], pah[3], vl2, vl3);
                MMA2(o[2*tp+1], pal[0], pal[1], pal[2], pal[3], vh2, vh3);
            }
        }
        __syncthreads();
    }

    // normalize + store bf16 hi + fp8 operands
    const float inv0 = 1.0f / l0;
    const float inv1 = 1.0f / l1;
    const int rowg = q0 + w * 16 + (lane >> 2);
    #pragma unroll
    for (int t = 0; t < 16; t++) {
        size_t g0 = ((size_t)(b * S_LEN + rowg)) * DM + head + t * 8 + (lane & 3) * 2;
        size_t g1 = g0 + 8 * DM;
        float v0 = o[t][0] * inv0, v1 = o[t][1] * inv0;
        float v2 = o[t][2] * inv1, v3 = o[t][3] * inv1;
        bf h0 = __float2bfloat16(v0), h1 = __float2bfloat16(v1);
        *(uint32_t*)(Oh + g0) = pack_bf2(h0, h1);
        *(uint16_t*)(Oqh + g0) = fp8x2(v0 * 0.25f, v1 * 0.25f);
        *(uint16_t*)(Oql + g0) = fp8x2((v0 - __bfloat162float(h0)) * 256.f,
                                       (v1 - __bfloat162float(h1)) * 256.f);
        bf h2 = __float2bfloat16(v2), h3 = __float2bfloat16(v3);
        *(uint32_t*)(Oh + g1) = pack_bf2(h2, h3);
        *(uint16_t*)(Oqh + g1) = fp8x2(v2 * 0.25f, v3 * 0.25f);
        *(uint16_t*)(Oql + g1) = fp8x2((v2 - __bfloat162float(h2)) * 256.f,
                                       (v3 - __bfloat162float(h3)) * 256.f);
    }
}

// ---------------------------------------------------------------------------
extern "C" void kernel_launch(void* const* d_in, const int* in_sizes, int n_in,
                              void* d_out, int out_size)
{
    const float* x  = (const float*)d_in[0];
    const float* wq = (const float*)d_in[1];
    const float* wk = (const float*)d_in[2];
    const float* wv = (const float*)d_in[3];
    const float* wo = (const float*)d_in[4];
    float* out = (float*)d_out;

    bf *xh, *qh, *ql, *kh, *kl, *vh, *vl, *ah, *wh;
    uint8_t *xqh, *xql, *aqh, *aql, *wqh, *wql;
    float *qf, *kf;
    cudaGetSymbolAddress((void**)&xh,  g_xh);
    cudaGetSymbolAddress((void**)&xqh, g_xqh);
    cudaGetSymbolAddress((void**)&xql, g_xql);
    cudaGetSymbolAddress((void**)&qf,  g_qf);
    cudaGetSymbolAddress((void**)&kf,  g_kf);
    cudaGetSymbolAddress((void**)&qh,  g_qh);
    cudaGetSymbolAddress((void**)&ql,  g_ql);
    cudaGetSymbolAddress((void**)&kh,  g_kh);
    cudaGetSymbolAddress((void**)&kl,  g_kl);
    cudaGetSymbolAddress((void**)&vh,  g_vh);
    cudaGetSymbolAddress((void**)&vl,  g_vl);
    cudaGetSymbolAddress((void**)&ah,  g_ah);
    cudaGetSymbolAddress((void**)&aqh, g_aqh);
    cudaGetSymbolAddress((void**)&aql, g_aql);
    cudaGetSymbolAddress((void**)&wh,  g_wh);
    cudaGetSymbolAddress((void**)&wqh, g_wqh);
    cudaGetSymbolAddress((void**)&wql, g_wql);
    const size_t WSZ = (size_t)DM * DM;

    convert_split_x<<<(M_TOT * (size_t)DM) / (256 * 8), 256>>>(x, xh, xqh, xql);
    dim3 tgrid(DM / 32, DM / 32), tblk(32, 8);
    transpose_convert<<<tgrid, tblk>>>(wq, wh + 0 * WSZ, wqh + 0 * WSZ, wql + 0 * WSZ);
    transpose_convert<<<tgrid, tblk>>>(wk, wh + 1 * WSZ, wqh + 1 * WSZ, wql + 1 * WSZ);
    transpose_convert<<<tgrid, tblk>>>(wv, wh + 2 * WSZ, wqh + 2 * WSZ, wql + 2 * WSZ);
    transpose_convert<<<tgrid, tblk>>>(wo, wh + 3 * WSZ, wqh + 3 * WSZ, wql + 3 * WSZ);

    cudaFuncSetAttribute(gemm_f8c<0>, cudaFuncAttributeMaxDynamicSharedMemorySize,
                         GEMM3_SMEM);
    cudaFuncSetAttribute(gemm_f8c<1>, cudaFuncAttributeMaxDynamicSharedMemorySize,
                         GEMM3_SMEM);
    dim3 ggrid(DM / 128, M_TOT / 128);
    gemm_f8c<0><<<ggrid, 512, GEMM3_SMEM>>>(xh, xqh, xql, wh + 0 * WSZ, wqh + 0 * WSZ,
        wql + 0 * WSZ, qf, nullptr, nullptr, M_TOT, DM, DM);
    gemm_f8c<0><<<ggrid, 512, GEMM3_SMEM>>>(xh, xqh, xql, wh + 1 * WSZ, wqh + 1 * WSZ,
        wql + 1 * WSZ, kf, nullptr, nullptr, M_TOT, DM, DM);
    gemm_f8c<1><<<ggrid, 512, GEMM3_SMEM>>>(xh, xqh, xql, wh + 2 * WSZ, wqh + 2 * WSZ,
        wql + 2 * WSZ, nullptr, vh, vl, M_TOT, DM, DM);

    int total_pairs = M_TOT * NH * (HD / 2);
    rope_convert<<<(total_pairs + 255) / 256, 256>>>(qf, kf, qh, ql, kh, kl, total_pairs);

    cudaFuncSetAttribute(flash_tc2, cudaFuncAttributeMaxDynamicSharedMemorySize,
                         FLASH_SMEM_BYTES);
    dim3 fgrid(S_LEN / 128, NH, B_SZ);
    flash_tc2<<<fgrid, 256, FLASH_SMEM_BYTES>>>(qh, ql, kh, kl, vh, vl, ah, aqh, aql);

    gemm_f8c<0><<<ggrid, 512, GEMM3_SMEM>>>(ah, aqh, aql, wh + 3 * WSZ, wqh + 3 * WSZ,
        wql + 3 * WSZ, out, nullptr, nullptr, M_TOT, DM, DM);
}

// round 8
// speedup vs baseline: 1.5774x; 1.5774x over previous
#include <cuda_runtime.h>
#include <cuda_bf16.h>
#include <cuda_fp16.h>
#include <cstdint>
#include <math.h>

#define B_SZ   4
#define S_LEN  2048
#define NH     16
#define HD     128
#define DM     2048
#define M_TOT  (B_SZ * S_LEN)
typedef __nv_bfloat16 bf;
typedef __half hf;

// ---------------- scratch (device globals; allocation-free) ----------------
__device__ __align__(128) hf    g_xh[(size_t)M_TOT * DM];
__device__ __align__(128) hf    g_xl[(size_t)M_TOT * DM];
__device__ __align__(128) float g_qf[(size_t)M_TOT * DM];
__device__ __align__(128) float g_kf[(size_t)M_TOT * DM];
__device__ __align__(128) bf    g_qh[(size_t)M_TOT * DM];
__device__ __align__(128) bf    g_ql[(size_t)M_TOT * DM];
__device__ __align__(128) bf    g_kh[(size_t)M_TOT * DM];
__device__ __align__(128) bf    g_kl[(size_t)M_TOT * DM];
__device__ __align__(128) hf    g_vh[(size_t)M_TOT * DM];
__device__ __align__(128) hf    g_vl[(size_t)M_TOT * DM];
__device__ __align__(128) hf    g_ah[(size_t)M_TOT * DM];
__device__ __align__(128) hf    g_al[(size_t)M_TOT * DM];
__device__ __align__(128) hf    g_wh[4][(size_t)DM * DM];    // weights, single fp16

// ---------------- helpers ----------------
__device__ __forceinline__ uint32_t smem_u32(const void* p) {
    uint32_t a;
    asm("{ .reg .u64 t; cvta.to.shared.u64 t, %1; cvt.u32.u64 %0, t; }"
        : "=r"(a) : "l"(p));
    return a;
}
__device__ __forceinline__ uint32_t pack_bf2(bf a, bf b) {
    __nv_bfloat162 t = __halves2bfloat162(a, b);
    return *reinterpret_cast<uint32_t*>(&t);
}
__device__ __forceinline__ uint32_t pack_h2(hf a, hf b) {
    __half2 t = __halves2half2(a, b);
    return *reinterpret_cast<uint32_t*>(&t);
}
__device__ __forceinline__ uint32_t pack_h2f(float a, float b) {
    __half2 t = __floats2half2_rn(a, b);
    return *reinterpret_cast<uint32_t*>(&t);
}
__device__ __forceinline__ void split1b(float v, bf& h, bf& l) {
    h = __float2bfloat16(v);
    l = __float2bfloat16(v - __bfloat162float(h));
}
__device__ __forceinline__ void split1h(float v, hf& h, hf& l) {
    h = __float2half_rn(v);
    l = __float2half_rn(v - __half2float(h));
}

// bf16 MMA (flash QK path)
#define MMA2(d, a0, a1, a2, a3, b0, b1)                                      \
    asm volatile(                                                            \
        "mma.sync.aligned.m16n8k16.row.col.f32.bf16.bf16.f32 "               \
        "{%0,%1,%2,%3}, {%4,%5,%6,%7}, {%8,%9}, {%0,%1,%2,%3};"              \
        : "+f"((d)[0]), "+f"((d)[1]), "+f"((d)[2]), "+f"((d)[3])             \
        : "r"(a0), "r"(a1), "r"(a2), "r"(a3), "r"(b0), "r"(b1))

// fp16 MMA (GEMMs + PV)
#define MMAH(d, a0, a1, a2, a3, b0, b1)                                      \
    asm volatile(                                                            \
        "mma.sync.aligned.m16n8k16.row.col.f32.f16.f16.f32 "                 \
        "{%0,%1,%2,%3}, {%4,%5,%6,%7}, {%8,%9}, {%0,%1,%2,%3};"              \
        : "+f"((d)[0]), "+f"((d)[1]), "+f"((d)[2]), "+f"((d)[3])             \
        : "r"(a0), "r"(a1), "r"(a2), "r"(a3), "r"(b0), "r"(b1))

#define LDMX4(r0, r1, r2, r3, addr)                                          \
    asm volatile("ldmatrix.sync.aligned.m8n8.x4.shared.b16 "                 \
        "{%0,%1,%2,%3}, [%4];"                                               \
        : "=r"(r0), "=r"(r1), "=r"(r2), "=r"(r3) : "r"(addr))

#define LDMX4T(r0, r1, r2, r3, addr)                                         \
    asm volatile("ldmatrix.sync.aligned.m8n8.x4.trans.shared.b16 "           \
        "{%0,%1,%2,%3}, [%4];"                                               \
        : "=r"(r0), "=r"(r1), "=r"(r2), "=r"(r3) : "r"(addr))

#define CP16(dst, src)                                                       \
    asm volatile("cp.async.cg.shared.global [%0], [%1], 16;"                 \
                 :: "r"(dst), "l"(src))
#define CP_COMMIT() asm volatile("cp.async.commit_group;" ::)
#define CP_WAIT(n)  asm volatile("cp.async.wait_group %0;" :: "n"(n))

// ---------------------------------------------------------------------------
// x: fp32 -> 2-term fp16 (hi, lo)
// ---------------------------------------------------------------------------
__global__ __launch_bounds__(256) void convert_split_x(
    const float* __restrict__ in, hf* __restrict__ H, hf* __restrict__ L)
{
    size_t base = ((size_t)blockIdx.x * 256 + threadIdx.x) * 8;
    #pragma unroll
    for (int j = 0; j < 2; j++) {
        float4 v = *(const float4*)(in + base + j * 4);
        hf hx, hy, hz, hw, lx, ly, lz, lw;
        split1h(v.x, hx, lx); split1h(v.y, hy, ly);
        split1h(v.z, hz, lz); split1h(v.w, hw, lw);
        *(uint2*)(H + base + j * 4) = make_uint2(pack_h2(hx, hy), pack_h2(hz, hw));
        *(uint2*)(L + base + j * 4) = make_uint2(pack_h2(lx, ly), pack_h2(lz, lw));
    }
}

// ---------------------------------------------------------------------------
// w [K,N] fp32 -> [N,K] single fp16
// ---------------------------------------------------------------------------
__global__ __launch_bounds__(256) void transpose_convert(
    const float* __restrict__ in, hf* __restrict__ H)
{
    __shared__ float t[32][33];
    int x = blockIdx.x * 32 + threadIdx.x;
    int y = blockIdx.y * 32 + threadIdx.y;
    #pragma unroll
    for (int i = 0; i < 4; i++)
        t[threadIdx.y + i * 8][threadIdx.x] = in[(size_t)(y + i * 8) * DM + x];
    __syncthreads();
    x = blockIdx.y * 32 + threadIdx.x;      // k index
    y = blockIdx.x * 32 + threadIdx.y;      // n index
    #pragma unroll
    for (int i = 0; i < 4; i++)
        H[(size_t)(y + i * 8) * DM + x] =
            __float2half_rn(t[threadIdx.x][threadIdx.y + i * 8]);
}

// ---------------------------------------------------------------------------
// GEMM: C[M,N] = A * B^T. A = (Ah, Al) 2-term fp16 [M,K]; B = Bh fp16 [N,K].
// 128x128 tile, K-chunk 32, 2-stage cp.async, ldmatrix, 2 MMAs / position.
// EPI=0: fp32 C.  EPI=1: 2-term fp16 (Ch, Cl).
// ---------------------------------------------------------------------------
#define GSTR   40
#define GA_EL  (128 * GSTR)                  // 5120 elems per array per stage
#define G_STAGE_BYTES (3 * GA_EL * 2)        // 30720
#define GEMM_SMEM_BYTES (2 * G_STAGE_BYTES)  // 61440

template<int EPI>
__global__ __launch_bounds__(256, 2) void gemm_2t(
    const hf* __restrict__ Ah, const hf* __restrict__ Al,
    const hf* __restrict__ Bh,
    float* __restrict__ C, hf* __restrict__ Ch, hf* __restrict__ Cl,
    int M, int N, int K)
{
    extern __shared__ __align__(16) char gsm[];
    const uint32_t sb = smem_u32(gsm);

    const int tid  = threadIdx.x;
    const int lane = tid & 31;
    const int wid  = tid >> 5;
    const int warpM = wid & 1;
    const int warpN = wid >> 1;
    const int n0 = blockIdx.x * 128;
    const int m0 = blockIdx.y * 128;

    const int lm = lane & 15, lh = lane >> 4;
    const int kb_row    = (lane >> 4) * 8 + (lane & 7);
    const int kb_coladd = ((lane >> 3) & 1) * 8;

    float acc[4][4][4];
    #pragma unroll
    for (int mt = 0; mt < 4; mt++)
        #pragma unroll
        for (int nt = 0; nt < 4; nt++)
            #pragma unroll
            for (int e = 0; e < 4; e++) acc[mt][nt][e] = 0.f;

    const int NK = K / 32;

    auto issue_stage = [&](int kt, int st) {
        const uint32_t sbase = sb + st * G_STAGE_BYTES;
        #pragma unroll
        for (int j = 0; j < 2; j++) {
            int idx = tid * 2 + j;
            int row = idx >> 2, ch = idx & 3;
            uint32_t doff = (uint32_t)(row * GSTR + ch * 8) * 2;
            size_t aoff = (size_t)(m0 + row) * K + kt * 32 + ch * 8;
            size_t boff = (size_t)(n0 + row) * K + kt * 32 + ch * 8;
            CP16(sbase + doff,                 Ah + aoff);
            CP16(sbase + GA_EL * 2 + doff,     Al + aoff);
            CP16(sbase + 2 * GA_EL * 2 + doff, Bh + boff);
        }
        CP_COMMIT();
    };

    issue_stage(0, 0);

    for (int kt = 0; kt < NK; kt++) {
        const int st = kt & 1;
        if (kt + 1 < NK) { issue_stage(kt + 1, st ^ 1); CP_WAIT(1); }
        else             { CP_WAIT(0); }
        __syncthreads();

        const uint32_t sbase = sb + st * G_STAGE_BYTES;
        #pragma unroll
        for (int kc = 0; kc < 2; kc++) {
            uint32_t ah[4][4], al[4][4], bh[2][4];
            #pragma unroll
            for (int mt = 0; mt < 4; mt++) {
                uint32_t aaddr = sbase +
                    (uint32_t)((warpM * 64 + mt * 16 + lm) * GSTR + kc * 16 + lh * 8) * 2;
                LDMX4(ah[mt][0], ah[mt][1], ah[mt][2], ah[mt][3], aaddr);
                LDMX4(al[mt][0], al[mt][1], al[mt][2], al[mt][3], aaddr + GA_EL * 2);
            }
            #pragma unroll
            for (int ng = 0; ng < 2; ng++) {
                uint32_t baddr = sbase + 2 * GA_EL * 2 +
                    (uint32_t)((warpN * 32 + ng * 16 + kb_row) * GSTR + kc * 16 + kb_coladd) * 2;
                LDMX4(bh[ng][0], bh[ng][1], bh[ng][2], bh[ng][3], baddr);
            }
            #pragma unroll
            for (int mt = 0; mt < 4; mt++)
                #pragma unroll
                for (int nt = 0; nt < 4; nt++) {
                    const int ng = nt >> 1, o = (nt & 1) * 2;
                    MMAH(acc[mt][nt], ah[mt][0], ah[mt][1], ah[mt][2], ah[mt][3],
                         bh[ng][o], bh[ng][o + 1]);
                    MMAH(acc[mt][nt], al[mt][0], al[mt][1], al[mt][2], al[mt][3],
                         bh[ng][o], bh[ng][o + 1]);
                }
        }
        __syncthreads();
    }

    const int mrow = lane >> 2;
    const int kcol = (lane & 3) * 2;
    #pragma unroll
    for (int mt = 0; mt < 4; mt++) {
        #pragma unroll
        for (int nt = 0; nt < 4; nt++) {
            int row = m0 + warpM * 64 + mt * 16 + mrow;
            int col = n0 + warpN * 32 + nt * 8 + kcol;
            if (EPI == 0) {
                *(float2*)(C + (size_t)row * N + col) =
                    make_float2(acc[mt][nt][0], acc[mt][nt][1]);
                *(float2*)(C + (size_t)(row + 8) * N + col) =
                    make_float2(acc[mt][nt][2], acc[mt][nt][3]);
            } else {
                hf h0, l0, h1, l1;
                split1h(acc[mt][nt][0], h0, l0);
                split1h(acc[mt][nt][1], h1, l1);
                *(uint32_t*)(Ch + (size_t)row * N + col) = pack_h2(h0, h1);
                *(uint32_t*)(Cl + (size_t)row * N + col) = pack_h2(l0, l1);
                split1h(acc[mt][nt][2], h0, l0);
                split1h(acc[mt][nt][3], h1, l1);
                *(uint32_t*)(Ch + (size_t)(row + 8) * N + col) = pack_h2(h0, h1);
                *(uint32_t*)(Cl + (size_t)(row + 8) * N + col) = pack_h2(l0, l1);
            }
        }
    }
}

// ---------------------------------------------------------------------------
// RoPE on fp32 q,k -> split bf16 (flash QK path); q scaled by 1/sqrt(H).
// ---------------------------------------------------------------------------
__global__ void rope_convert(
    const float* __restrict__ q, const float* __restrict__ k,
    bf* __restrict__ qh, bf* __restrict__ ql,
    bf* __restrict__ kh, bf* __restrict__ kl, int total)
{
    int idx = blockIdx.x * blockDim.x + threadIdx.x;
    if (idx >= total) return;
    int pair = idx & 63;
    int m    = idx >> 10;
    int s    = m & (S_LEN - 1);

    float fraction  = (2.0f * (float)pair) / (float)HD;
    float timescale = exp2f(fraction * 13.287712379549449f);
    float ang = (float)s / timescale;
    float sv, cv;
    sincosf(ang, &sv, &cv);

    size_t base = (size_t)m * DM + (size_t)((idx >> 6) & (NH - 1)) * HD + pair * 2;
    const float qs = 0.08838834764831845f;

    float q1 = q[base], q2 = q[base + 1];
    float r1 = (q1 * cv - q2 * sv) * qs;
    float r2 = (q2 * cv + q1 * sv) * qs;
    bf h1, l1, h2, l2;
    split1b(r1, h1, l1); split1b(r2, h2, l2);
    *(uint32_t*)(qh + base) = pack_bf2(h1, h2);
    *(uint32_t*)(ql + base) = pack_bf2(l1, l2);

    float k1 = k[base], k2 = k[base + 1];
    r1 = k1 * cv - k2 * sv;
    r2 = k2 * cv + k1 * sv;
    split1b(r1, h1, l1); split1b(r2, h2, l2);
    *(uint32_t*)(kh + base) = pack_bf2(h1, h2);
    *(uint32_t*)(kl + base) = pack_bf2(l1, l2);
}

// ---------------------------------------------------------------------------
// Flash attention: QK bf16x3, PV fp16 (P single, V 2-term).
// CTA: (128-row q tile, head, batch), 8 warps, double-buffered K/V cp.async.
// Output: 2-term fp16 attn.
// ---------------------------------------------------------------------------
#define FSTR    136
#define F_QH    0
#define F_QL    (128 * FSTR)
#define F_KV0   (2 * 128 * FSTR)
#define F_KVSZ  (4 * 64 * FSTR)
#define LO_OFF  (64 * FSTR)
#define FLASH_SMEM_BYTES ((F_KV0 + 2 * F_KVSZ) * 2)

__global__ __launch_bounds__(256, 1) void flash_tc3(
    const bf* __restrict__ Qh, const bf* __restrict__ Ql,
    const bf* __restrict__ Kh, const bf* __restrict__ Kl,
    const hf* __restrict__ Vh, const hf* __restrict__ Vl,
    hf* __restrict__ Oh, hf* __restrict__ Ol)
{
    extern __shared__ __align__(16) char fsm[];
    const uint32_t sb = smem_u32(fsm);

    const int tid  = threadIdx.x;
    const int lane = tid & 31;
    const int w    = tid >> 5;
    const int qt   = blockIdx.x;
    const int hN   = blockIdx.y;
    const int b    = blockIdx.z;
    const int q0   = qt * 128;
    const size_t head = (size_t)hN * HD;

    auto issue_kv = [&](int kt, int st) {
        const int k0 = kt * 64;
        const uint32_t base = sb + (F_KV0 + st * F_KVSZ) * 2;
        #pragma unroll
        for (int i = 0; i < 4; i++) {
            int idx = tid + i * 256;
            int row = idx >> 4, ch = idx & 15;
            uint32_t doff = (uint32_t)(row * FSTR + ch * 8) * 2;
            size_t g = ((size_t)(b * S_LEN + k0 + row)) * DM + head + ch * 8;
            CP16(base + doff,                  Kh + g);
            CP16(base + LO_OFF * 2 + doff,     Kl + g);
            CP16(base + 2 * LO_OFF * 2 + doff, Vh + g);
            CP16(base + 3 * LO_OFF * 2 + doff, Vl + g);
        }
        CP_COMMIT();
    };

    #pragma unroll
    for (int i = 0; i < 8; i++) {
        int idx = tid + i * 256;
        int row = idx >> 4, ch = idx & 15;
        uint32_t doff = (uint32_t)(row * FSTR + ch * 8) * 2;
        size_t g = ((size_t)(b * S_LEN + q0 + row)) * DM + head + ch * 8;
        CP16(sb + doff,            Qh + g);
        CP16(sb + F_QL * 2 + doff, Ql + g);
    }
    issue_kv(0, 0);

    float m0 = -1e30f, m1 = -1e30f, l0 = 0.f, l1 = 0.f;
    float o[16][4];
    #pragma unroll
    for (int t = 0; t < 16; t++)
        #pragma unroll
        for (int e = 0; e < 4; e++) o[t][e] = 0.f;

    const int ktiles = 2 * qt + 2;

    const uint32_t qa_base =
        sb + ((w * 16 + (lane & 15)) * FSTR + (lane >> 4) * 8) * 2;
    const uint32_t kb_row    = (lane >> 4) * 8 + (lane & 7);
    const uint32_t kb_coladd = ((lane >> 3) & 1) * 8;
    const uint32_t vb_rowadd = ((lane >> 3) & 1) * 8 + (lane & 7);
    const uint32_t vb_coladd = (lane >> 4) * 8;

    for (int kt = 0; kt < ktiles; kt++) {
        const int st = kt & 1;
        if (kt + 1 < ktiles) { issue_kv(kt + 1, st ^ 1); CP_WAIT(1); }
        else                 { CP_WAIT(0); }
        __syncthreads();

        const uint32_t khb = F_KV0 + st * F_KVSZ;
        const uint32_t vhb = khb + 2 * LO_OFF;

        // ---- S = Q K^T (bf16 x3) ----
        float c[8][4];
        #pragma unroll
        for (int t = 0; t < 8; t++)
            #pragma unroll
            for (int e = 0; e < 4; e++) c[t][e] = 0.f;

        #pragma unroll
        for (int kc = 0; kc < 8; kc++) {
            uint32_t ah0, ah1, ah2, ah3, al0, al1, al2, al3;
            uint32_t qaddr = qa_base + kc * 32;
            LDMX4(ah0, ah1, ah2, ah3, qaddr);
            LDMX4(al0, al1, al2, al3, qaddr + F_QL * 2);
            #pragma unroll
            for (int tp = 0; tp < 4; tp++) {
                uint32_t bh0, bh1, bh2, bh3, bl0, bl1, bl2, bl3;
                uint32_t kaddr = sb +
                    (khb + (tp * 16 + kb_row) * FSTR + kc * 16 + kb_coladd) * 2;
                LDMX4(bh0, bh1, bh2, bh3, kaddr);
                LDMX4(bl0, bl1, bl2, bl3, kaddr + LO_OFF * 2);
                MMA2(c[2*tp],   ah0, ah1, ah2, ah3, bh0, bh1);
                MMA2(c[2*tp],   ah0, ah1, ah2, ah3, bl0, bl1);
                MMA2(c[2*tp],   al0, al1, al2, al3, bh0, bh1);
                MMA2(c[2*tp+1], ah0, ah1, ah2, ah3, bh2, bh3);
                MMA2(c[2*tp+1], ah0, ah1, ah2, ah3, bl2, bl3);
                MMA2(c[2*tp+1], al0, al1, al2, al3, bh2, bh3);
            }
        }

        // ---- causal mask on diagonal tiles ----
        const int rowg0 = q0 + w * 16 + (lane >> 2);
        if (kt >= 2 * qt) {
            const int k0 = kt * 64;
            #pragma unroll
            for (int t = 0; t < 8; t++) {
                int colb = k0 + t * 8 + (lane & 3) * 2;
                if (colb     > rowg0)     c[t][0] = -1e30f;
                if (colb + 1 > rowg0)     c[t][1] = -1e30f;
                if (colb     > rowg0 + 8) c[t][2] = -1e30f;
                if (colb + 1 > rowg0 + 8) c[t][3] = -1e30f;
            }
        }

        // ---- online softmax ----
        float mx0 = -1e30f, mx1 = -1e30f;
        #pragma unroll
        for (int t = 0; t < 8; t++) {
            mx0 = fmaxf(mx0, fmaxf(c[t][0], c[t][1]));
            mx1 = fmaxf(mx1, fmaxf(c[t][2], c[t][3]));
        }
        mx0 = fmaxf(mx0, __shfl_xor_sync(0xffffffffu, mx0, 1));
        mx0 = fmaxf(mx0, __shfl_xor_sync(0xffffffffu, mx0, 2));
        mx1 = fmaxf(mx1, __shfl_xor_sync(0xffffffffu, mx1, 1));
        mx1 = fmaxf(mx1, __shfl_xor_sync(0xffffffffu, mx1, 2));
        const float mn0 = fmaxf(m0, mx0);
        const float mn1 = fmaxf(m1, mx1);
        const float sc0 = __expf(m0 - mn0);
        const float sc1 = __expf(m1 - mn1);
        float sum0 = 0.f, sum1 = 0.f;
        #pragma unroll
        for (int t = 0; t < 8; t++) {
            c[t][0] = __expf(c[t][0] - mn0); sum0 += c[t][0];
            c[t][1] = __expf(c[t][1] - mn0); sum0 += c[t][1];
            c[t][2] = __expf(c[t][2] - mn1); sum1 += c[t][2];
            c[t][3] = __expf(c[t][3] - mn1); sum1 += c[t][3];
        }
        sum0 += __shfl_xor_sync(0xffffffffu, sum0, 1);
        sum0 += __shfl_xor_sync(0xffffffffu, sum0, 2);
        sum1 += __shfl_xor_sync(0xffffffffu, sum1, 1);
        sum1 += __shfl_xor_sync(0xffffffffu, sum1, 2);
        m0 = mn0; m1 = mn1;
        l0 = l0 * sc0 + sum0;
        l1 = l1 * sc1 + sum1;
        #pragma unroll
        for (int t = 0; t < 16; t++) {
            o[t][0] *= sc0; o[t][1] *= sc0;
            o[t][2] *= sc1; o[t][3] *= sc1;
        }

        // ---- O += P V  (P single fp16, V 2-term fp16) ----
        #pragma unroll
        for (int kc = 0; kc < 4; kc++) {
            uint32_t pa[4];
            #pragma unroll
            for (int half = 0; half < 2; half++) {
                const int t = 2 * kc + half;
                pa[2*half]   = pack_h2f(c[t][0], c[t][1]);
                pa[2*half+1] = pack_h2f(c[t][2], c[t][3]);
            }
            #pragma unroll
            for (int tp = 0; tp < 8; tp++) {
                uint32_t vh0, vh1, vh2, vh3, vl0, vl1, vl2, vl3;
                uint32_t vaddr = sb +
                    (vhb + (kc * 16 + vb_rowadd) * FSTR + tp * 16 + vb_coladd) * 2;
                LDMX4T(vh0, vh1, vh2, vh3, vaddr);
                LDMX4T(vl0, vl1, vl2, vl3, vaddr + LO_OFF * 2);
                MMAH(o[2*tp],   pa[0], pa[1], pa[2], pa[3], vh0, vh1);
                MMAH(o[2*tp],   pa[0], pa[1], pa[2], pa[3], vl0, vl1);
                MMAH(o[2*tp+1], pa[0], pa[1], pa[2], pa[3], vh2, vh3);
                MMAH(o[2*tp+1], pa[0], pa[1], pa[2], pa[3], vl2, vl3);
            }
        }
        __syncthreads();
    }

    // ---- normalize + 2-term fp16 store ----
    const float inv0 = 1.0f / l0;
    const float inv1 = 1.0f / l1;
    const int rowg = q0 + w * 16 + (lane >> 2);
    #pragma unroll
    for (int t = 0; t < 16; t++) {
        size_t g0 = ((size_t)(b * S_LEN + rowg)) * DM + head + t * 8 + (lane & 3) * 2;
        size_t g1 = g0 + 8 * DM;
        hf h0, l0b, h1, l1b;
        split1h(o[t][0] * inv0, h0, l0b);
        split1h(o[t][1] * inv0, h1, l1b);
        *(uint32_t*)(Oh + g0) = pack_h2(h0, h1);
        *(uint32_t*)(Ol + g0) = pack_h2(l0b, l1b);
        split1h(o[t][2] * inv1, h0, l0b);
        split1h(o[t][3] * inv1, h1, l1b);
        *(uint32_t*)(Oh + g1) = pack_h2(h0, h1);
        *(uint32_t*)(Ol + g1) = pack_h2(l0b, l1b);
    }
}

// ---------------------------------------------------------------------------
extern "C" void kernel_launch(void* const* d_in, const int* in_sizes, int n_in,
                              void* d_out, int out_size)
{
    const float* x  = (const float*)d_in[0];
    const float* wq = (const float*)d_in[1];
    const float* wk = (const float*)d_in[2];
    const float* wv = (const float*)d_in[3];
    const float* wo = (const float*)d_in[4];
    float* out = (float*)d_out;

    hf *xh, *xl, *vh, *vl, *ah, *al, *wh;
    bf *qh, *ql, *kh, *kl;
    float *qf, *kf;
    cudaGetSymbolAddress((void**)&xh, g_xh);
    cudaGetSymbolAddress((void**)&xl, g_xl);
    cudaGetSymbolAddress((void**)&qf, g_qf);
    cudaGetSymbolAddress((void**)&kf, g_kf);
    cudaGetSymbolAddress((void**)&qh, g_qh);
    cudaGetSymbolAddress((void**)&ql, g_ql);
    cudaGetSymbolAddress((void**)&kh, g_kh);
    cudaGetSymbolAddress((void**)&kl, g_kl);
    cudaGetSymbolAddress((void**)&vh, g_vh);
    cudaGetSymbolAddress((void**)&vl, g_vl);
    cudaGetSymbolAddress((void**)&ah, g_ah);
    cudaGetSymbolAddress((void**)&al, g_al);
    cudaGetSymbolAddress((void**)&wh, g_wh);
    const size_t WSZ = (size_t)DM * DM;

    convert_split_x<<<(M_TOT * (size_t)DM) / (256 * 8), 256>>>(x, xh, xl);
    dim3 tgrid(DM / 32, DM / 32), tblk(32, 8);
    transpose_convert<<<tgrid, tblk>>>(wq, wh + 0 * WSZ);
    transpose_convert<<<tgrid, tblk>>>(wk, wh + 1 * WSZ);
    transpose_convert<<<tgrid, tblk>>>(wv, wh + 2 * WSZ);
    transpose_convert<<<tgrid, tblk>>>(wo, wh + 3 * WSZ);

    cudaFuncSetAttribute(gemm_2t<0>, cudaFuncAttributeMaxDynamicSharedMemorySize,
                         GEMM_SMEM_BYTES);
    cudaFuncSetAttribute(gemm_2t<1>, cudaFuncAttributeMaxDynamicSharedMemorySize,
                         GEMM_SMEM_BYTES);
    dim3 ggrid(DM / 128, M_TOT / 128);
    gemm_2t<0><<<ggrid, 256, GEMM_SMEM_BYTES>>>(xh, xl, wh + 0 * WSZ,
        qf, nullptr, nullptr, M_TOT, DM, DM);
    gemm_2t<0><<<ggrid, 256, GEMM_SMEM_BYTES>>>(xh, xl, wh + 1 * WSZ,
        kf, nullptr, nullptr, M_TOT, DM, DM);
    gemm_2t<1><<<ggrid, 256, GEMM_SMEM_BYTES>>>(xh, xl, wh + 2 * WSZ,
        nullptr, vh, vl, M_TOT, DM, DM);

    int total_pairs = M_TOT * NH * (HD / 2);
    rope_convert<<<(total_pairs + 255) / 256, 256>>>(qf, kf, qh, ql, kh, kl, total_pairs);

    cudaFuncSetAttribute(flash_tc3, cudaFuncAttributeMaxDynamicSharedMemorySize,
                         FLASH_SMEM_BYTES);
    dim3 fgrid(S_LEN / 128, NH, B_SZ);
    flash_tc3<<<fgrid, 256, FLASH_SMEM_BYTES>>>(qh, ql, kh, kl, vh, vl, ah, al);

    gemm_2t<0><<<ggrid, 256, GEMM_SMEM_BYTES>>>(ah, al, wh + 3 * WSZ,
        out, nullptr, nullptr, M_TOT, DM, DM);
}

// round 9
// speedup vs baseline: 2.4429x; 1.5487x over previous
#include <cuda_runtime.h>
#include <cuda_fp16.h>
#include <cstdint>
#include <math.h>

#define B_SZ   4
#define S_LEN  2048
#define NH     16
#define HD     128
#define DM     2048
#define M_TOT  (B_SZ * S_LEN)
typedef __half hf;

// ---------------- scratch (device globals; allocation-free) ----------------
__device__ __align__(128) hf g_xh[(size_t)M_TOT * DM];
__device__ __align__(128) hf g_qh[(size_t)M_TOT * DM];
__device__ __align__(128) hf g_kh[(size_t)M_TOT * DM];
__device__ __align__(128) hf g_vh[(size_t)M_TOT * DM];
__device__ __align__(128) hf g_ah[(size_t)M_TOT * DM];
__device__ __align__(128) hf g_al[(size_t)M_TOT * DM];
__device__ __align__(128) hf g_wh[4][(size_t)DM * DM];

// ---------------- helpers ----------------
__device__ __forceinline__ uint32_t smem_u32(const void* p) {
    uint32_t a;
    asm("{ .reg .u64 t; cvta.to.shared.u64 t, %1; cvt.u32.u64 %0, t; }"
        : "=r"(a) : "l"(p));
    return a;
}
__device__ __forceinline__ uint32_t pack_h2(hf a, hf b) {
    __half2 t = __halves2half2(a, b);
    return *reinterpret_cast<uint32_t*>(&t);
}
__device__ __forceinline__ uint32_t pack_h2f(float a, float b) {
    __half2 t = __floats2half2_rn(a, b);
    return *reinterpret_cast<uint32_t*>(&t);
}
__device__ __forceinline__ void split1h(float v, hf& h, hf& l) {
    h = __float2half_rn(v);
    l = __float2half_rn(v - __half2float(h));
}

#define MMAH(d, a0, a1, a2, a3, b0, b1)                                      \
    asm volatile(                                                            \
        "mma.sync.aligned.m16n8k16.row.col.f32.f16.f16.f32 "                 \
        "{%0,%1,%2,%3}, {%4,%5,%6,%7}, {%8,%9}, {%0,%1,%2,%3};"              \
        : "+f"((d)[0]), "+f"((d)[1]), "+f"((d)[2]), "+f"((d)[3])             \
        : "r"(a0), "r"(a1), "r"(a2), "r"(a3), "r"(b0), "r"(b1))

#define LDMX4(r0, r1, r2, r3, addr)                                          \
    asm volatile("ldmatrix.sync.aligned.m8n8.x4.shared.b16 "                 \
        "{%0,%1,%2,%3}, [%4];"                                               \
        : "=r"(r0), "=r"(r1), "=r"(r2), "=r"(r3) : "r"(addr))

#define LDMX4T(r0, r1, r2, r3, addr)                                         \
    asm volatile("ldmatrix.sync.aligned.m8n8.x4.trans.shared.b16 "           \
        "{%0,%1,%2,%3}, [%4];"                                               \
        : "=r"(r0), "=r"(r1), "=r"(r2), "=r"(r3) : "r"(addr))

#define CP16(dst, src)                                                       \
    asm volatile("cp.async.cg.shared.global [%0], [%1], 16;"                 \
                 :: "r"(dst), "l"(src))
#define CP_COMMIT() asm volatile("cp.async.commit_group;" ::)
#define CP_WAIT(n)  asm volatile("cp.async.wait_group %0;" :: "n"(n))

// ---------------------------------------------------------------------------
// x: fp32 -> single fp16
// ---------------------------------------------------------------------------
__global__ __launch_bounds__(256) void convert_x(
    const float* __restrict__ in, hf* __restrict__ H)
{
    size_t base = ((size_t)blockIdx.x * 256 + threadIdx.x) * 8;
    float4 v0 = *(const float4*)(in + base);
    float4 v1 = *(const float4*)(in + base + 4);
    uint4 hv;
    hv.x = pack_h2f(v0.x, v0.y); hv.y = pack_h2f(v0.z, v0.w);
    hv.z = pack_h2f(v1.x, v1.y); hv.w = pack_h2f(v1.z, v1.w);
    *(uint4*)(H + base) = hv;
}

// ---------------------------------------------------------------------------
// w [K,N] fp32 -> [N,K] single fp16
// ---------------------------------------------------------------------------
__global__ __launch_bounds__(256) void transpose_convert(
    const float* __restrict__ in, hf* __restrict__ H)
{
    __shared__ float t[32][33];
    int x = blockIdx.x * 32 + threadIdx.x;
    int y = blockIdx.y * 32 + threadIdx.y;
    #pragma unroll
    for (int i = 0; i < 4; i++)
        t[threadIdx.y + i * 8][threadIdx.x] = in[(size_t)(y + i * 8) * DM + x];
    __syncthreads();
    x = blockIdx.y * 32 + threadIdx.x;
    y = blockIdx.x * 32 + threadIdx.y;
    #pragma unroll
    for (int i = 0; i < 4; i++)
        H[(size_t)(y + i * 8) * DM + x] =
            __float2half_rn(t[threadIdx.x][threadIdx.y + i * 8]);
}

// ---------------------------------------------------------------------------
// GEMM-1term: C = A * B^T, A/B single fp16, 1 MMA per position.
// 128x128 tile, 256 thr (8 warps 2x4), K-chunk 32, 3-stage cp.async.
// EPI: 1 = plain fp16 out; 2 = RoPE+qscale fp16 out (q); 3 = RoPE fp16 out (k)
// ---------------------------------------------------------------------------
#define GSTR   40
#define GA_EL  (128 * GSTR)
#define G1_STAGE_BYTES (2 * GA_EL * 2)          // 20480
#define GEMM1_SMEM (3 * G1_STAGE_BYTES)         // 61440

__device__ __forceinline__ void rope_pair(
    int row, int col, float& v0, float& v1, float scale)
{
    int s = row & (S_LEN - 1);
    int i = (col & (HD - 1)) >> 1;
    float fraction  = (2.0f * (float)i) / (float)HD;
    float timescale = exp2f(fraction * 13.287712379549449f); // log2(10000)
    float ang = (float)s / timescale;
    float sv, cv;
    sincosf(ang, &sv, &cv);
    float r0 = (v0 * cv - v1 * sv) * scale;
    float r1 = (v1 * cv + v0 * sv) * scale;
    v0 = r0; v1 = r1;
}

template<int EPI>
__global__ __launch_bounds__(256, 2) void gemm_1t(
    const hf* __restrict__ A, const hf* __restrict__ B,
    hf* __restrict__ Ch, int M, int N, int K)
{
    extern __shared__ __align__(16) char gsm[];
    const uint32_t sb = smem_u32(gsm);

    const int tid  = threadIdx.x;
    const int lane = tid & 31;
    const int wid  = tid >> 5;
    const int warpM = wid & 1;
    const int warpN = wid >> 1;
    const int n0 = blockIdx.x * 128;
    const int m0 = blockIdx.y * 128;

    const int lm = lane & 15, lh = lane >> 4;
    const int kb_row    = (lane >> 4) * 8 + (lane & 7);
    const int kb_coladd = ((lane >> 3) & 1) * 8;

    float acc[4][4][4];
    #pragma unroll
    for (int mt = 0; mt < 4; mt++)
        #pragma unroll
        for (int nt = 0; nt < 4; nt++)
            #pragma unroll
            for (int e = 0; e < 4; e++) acc[mt][nt][e] = 0.f;

    const int NK = K / 32;

    auto issue_stage = [&](int kt) {
        const uint32_t sbase = sb + (uint32_t)(kt % 3) * G1_STAGE_BYTES;
        #pragma unroll
        for (int j = 0; j < 2; j++) {
            int idx = tid * 2 + j;
            int row = idx >> 2, ch = idx & 3;
            uint32_t doff = (uint32_t)(row * GSTR + ch * 8) * 2;
            CP16(sbase + doff,             A + (size_t)(m0 + row) * K + kt * 32 + ch * 8);
            CP16(sbase + GA_EL * 2 + doff, B + (size_t)(n0 + row) * K + kt * 32 + ch * 8);
        }
        CP_COMMIT();
    };

    issue_stage(0);
    issue_stage(1);

    for (int kt = 0; kt < NK; kt++) {
        if (kt + 1 < NK) CP_WAIT(1); else CP_WAIT(0);
        __syncthreads();
        if (kt + 2 < NK) issue_stage(kt + 2);

        const uint32_t sbase = sb + (uint32_t)(kt % 3) * G1_STAGE_BYTES;
        #pragma unroll
        for (int kc = 0; kc < 2; kc++) {
            uint32_t ah[4][4], bh[2][4];
            #pragma unroll
            for (int mt = 0; mt < 4; mt++) {
                uint32_t aaddr = sbase +
                    (uint32_t)((warpM * 64 + mt * 16 + lm) * GSTR + kc * 16 + lh * 8) * 2;
                LDMX4(ah[mt][0], ah[mt][1], ah[mt][2], ah[mt][3], aaddr);
            }
            #pragma unroll
            for (int ng = 0; ng < 2; ng++) {
                uint32_t baddr = sbase + GA_EL * 2 +
                    (uint32_t)((warpN * 32 + ng * 16 + kb_row) * GSTR + kc * 16 + kb_coladd) * 2;
                LDMX4(bh[ng][0], bh[ng][1], bh[ng][2], bh[ng][3], baddr);
            }
            #pragma unroll
            for (int mt = 0; mt < 4; mt++)
                #pragma unroll
                for (int nt = 0; nt < 4; nt++) {
                    const int ng = nt >> 1, o = (nt & 1) * 2;
                    MMAH(acc[mt][nt], ah[mt][0], ah[mt][1], ah[mt][2], ah[mt][3],
                         bh[ng][o], bh[ng][o + 1]);
                }
        }
        __syncthreads();
    }

    const int mrow = lane >> 2;
    const int kcol = (lane & 3) * 2;    // even -> (col, col+1) is a RoPE pair
    const float qs = (EPI == 2) ? 0.08838834764831845f : 1.0f;
    #pragma unroll
    for (int mt = 0; mt < 4; mt++) {
        #pragma unroll
        for (int nt = 0; nt < 4; nt++) {
            int row = m0 + warpM * 64 + mt * 16 + mrow;
            int col = n0 + warpN * 32 + nt * 8 + kcol;
            float v0 = acc[mt][nt][0], v1 = acc[mt][nt][1];
            float v2 = acc[mt][nt][2], v3 = acc[mt][nt][3];
            if (EPI >= 2) {
                rope_pair(row,     col, v0, v1, qs);
                rope_pair(row + 8, col, v2, v3, qs);
            }
            *(uint32_t*)(Ch + (size_t)row * N + col)       = pack_h2f(v0, v1);
            *(uint32_t*)(Ch + (size_t)(row + 8) * N + col) = pack_h2f(v2, v3);
        }
    }
}

// ---------------------------------------------------------------------------
// GEMM-2term (out-proj): A = (Ah, Al) 2-term fp16, B single fp16, fp32 out.
// ---------------------------------------------------------------------------
#define G2_STAGE_BYTES (3 * GA_EL * 2)          // 30720
#define GEMM2_SMEM (2 * G2_STAGE_BYTES)         // 61440

__global__ __launch_bounds__(256, 2) void gemm_2t(
    const hf* __restrict__ Ah, const hf* __restrict__ Al,
    const hf* __restrict__ Bh, float* __restrict__ C,
    int M, int N, int K)
{
    extern __shared__ __align__(16) char gsm[];
    const uint32_t sb = smem_u32(gsm);

    const int tid  = threadIdx.x;
    const int lane = tid & 31;
    const int wid  = tid >> 5;
    const int warpM = wid & 1;
    const int warpN = wid >> 1;
    const int n0 = blockIdx.x * 128;
    const int m0 = blockIdx.y * 128;

    const int lm = lane & 15, lh = lane >> 4;
    const int kb_row    = (lane >> 4) * 8 + (lane & 7);
    const int kb_coladd = ((lane >> 3) & 1) * 8;

    float acc[4][4][4];
    #pragma unroll
    for (int mt = 0; mt < 4; mt++)
        #pragma unroll
        for (int nt = 0; nt < 4; nt++)
            #pragma unroll
            for (int e = 0; e < 4; e++) acc[mt][nt][e] = 0.f;

    const int NK = K / 32;

    auto issue_stage = [&](int kt, int st) {
        const uint32_t sbase = sb + st * G2_STAGE_BYTES;
        #pragma unroll
        for (int j = 0; j < 2; j++) {
            int idx = tid * 2 + j;
            int row = idx >> 2, ch = idx & 3;
            uint32_t doff = (uint32_t)(row * GSTR + ch * 8) * 2;
            size_t aoff = (size_t)(m0 + row) * K + kt * 32 + ch * 8;
            size_t boff = (size_t)(n0 + row) * K + kt * 32 + ch * 8;
            CP16(sbase + doff,                 Ah + aoff);
            CP16(sbase + GA_EL * 2 + doff,     Al + aoff);
            CP16(sbase + 2 * GA_EL * 2 + doff, Bh + boff);
        }
        CP_COMMIT();
    };

    issue_stage(0, 0);

    for (int kt = 0; kt < NK; kt++) {
        const int st = kt & 1;
        if (kt + 1 < NK) { issue_stage(kt + 1, st ^ 1); CP_WAIT(1); }
        else             { CP_WAIT(0); }
        __syncthreads();

        const uint32_t sbase = sb + st * G2_STAGE_BYTES;
        #pragma unroll
        for (int kc = 0; kc < 2; kc++) {
            uint32_t ah[4][4], al[4][4], bh[2][4];
            #pragma unroll
            for (int mt = 0; mt < 4; mt++) {
                uint32_t aaddr = sbase +
                    (uint32_t)((warpM * 64 + mt * 16 + lm) * GSTR + kc * 16 + lh * 8) * 2;
                LDMX4(ah[mt][0], ah[mt][1], ah[mt][2], ah[mt][3], aaddr);
                LDMX4(al[mt][0], al[mt][1], al[mt][2], al[mt][3], aaddr + GA_EL * 2);
            }
            #pragma unroll
            for (int ng = 0; ng < 2; ng++) {
                uint32_t baddr = sbase + 2 * GA_EL * 2 +
                    (uint32_t)((warpN * 32 + ng * 16 + kb_row) * GSTR + kc * 16 + kb_coladd) * 2;
                LDMX4(bh[ng][0], bh[ng][1], bh[ng][2], bh[ng][3], baddr);
            }
            #pragma unroll
            for (int mt = 0; mt < 4; mt++)
                #pragma unroll
                for (int nt = 0; nt < 4; nt++) {
                    const int ng = nt >> 1, o = (nt & 1) * 2;
                    MMAH(acc[mt][nt], ah[mt][0], ah[mt][1], ah[mt][2], ah[mt][3],
                         bh[ng][o], bh[ng][o + 1]);
                    MMAH(acc[mt][nt], al[mt][0], al[mt][1], al[mt][2], al[mt][3],
                         bh[ng][o], bh[ng][o + 1]);
                }
        }
        __syncthreads();
    }

    const int mrow = lane >> 2;
    const int kcol = (lane & 3) * 2;
    #pragma unroll
    for (int mt = 0; mt < 4; mt++) {
        #pragma unroll
        for (int nt = 0; nt < 4; nt++) {
            int row = m0 + warpM * 64 + mt * 16 + mrow;
            int col = n0 + warpN * 32 + nt * 8 + kcol;
            *(float2*)(C + (size_t)row * N + col) =
                make_float2(acc[mt][nt][0], acc[mt][nt][1]);
            *(float2*)(C + (size_t)(row + 8) * N + col) =
                make_float2(acc[mt][nt][2], acc[mt][nt][3]);
        }
    }
}

// ---------------------------------------------------------------------------
// Flash attention: Q,K,V single fp16 (1 MMA per fragment in QK and PV).
// CTA: (128-row q tile, head, batch), 8 warps, double-buffered K/V cp.async.
// Output: 2-term fp16 attn (for the 2-term out-proj).
// ---------------------------------------------------------------------------
#define FSTR    136
#define F_Q     0
#define F_KV0   (128 * FSTR)
#define F_KVSZ  (2 * 64 * FSTR)
#define V_OFF   (64 * FSTR)
#define FLASH_SMEM_BYTES ((F_KV0 + 2 * F_KVSZ) * 2)   // 104448

__global__ __launch_bounds__(256, 1) void flash_tc4(
    const hf* __restrict__ Qh, const hf* __restrict__ Kh,
    const hf* __restrict__ Vh,
    hf* __restrict__ Oh, hf* __restrict__ Ol)
{
    extern __shared__ __align__(16) char fsm[];
    const uint32_t sb = smem_u32(fsm);

    const int tid  = threadIdx.x;
    const int lane = tid & 31;
    const int w    = tid >> 5;
    const int qt   = blockIdx.x;
    const int hN   = blockIdx.y;
    const int b    = blockIdx.z;
    const int q0   = qt * 128;
    const size_t head = (size_t)hN * HD;

    auto issue_kv = [&](int kt, int st) {
        const int k0 = kt * 64;
        const uint32_t base = sb + (F_KV0 + st * F_KVSZ) * 2;
        #pragma unroll
        for (int i = 0; i < 4; i++) {
            int idx = tid + i * 256;            // 0..1023
            int row = idx >> 4, ch = idx & 15;
            uint32_t doff = (uint32_t)(row * FSTR + ch * 8) * 2;
            size_t g = ((size_t)(b * S_LEN + k0 + row)) * DM + head + ch * 8;
            CP16(base + doff,             Kh + g);
            CP16(base + V_OFF * 2 + doff, Vh + g);
        }
        CP_COMMIT();
    };

    #pragma unroll
    for (int i = 0; i < 8; i++) {
        int idx = tid + i * 256;                // 0..2047
        int row = idx >> 4, ch = idx & 15;
        uint32_t doff = (uint32_t)(row * FSTR + ch * 8) * 2;
        size_t g = ((size_t)(b * S_LEN + q0 + row)) * DM + head + ch * 8;
        CP16(sb + doff, Qh + g);
    }
    issue_kv(0, 0);

    float m0 = -1e30f, m1 = -1e30f, l0 = 0.f, l1 = 0.f;
    float o[16][4];
    #pragma unroll
    for (int t = 0; t < 16; t++)
        #pragma unroll
        for (int e = 0; e < 4; e++) o[t][e] = 0.f;

    const int ktiles = 2 * qt + 2;

    const uint32_t qa_base =
        sb + ((w * 16 + (lane & 15)) * FSTR + (lane >> 4) * 8) * 2;
    const uint32_t kb_row    = (lane >> 4) * 8 + (lane & 7);
    const uint32_t kb_coladd = ((lane >> 3) & 1) * 8;
    const uint32_t vb_rowadd = ((lane >> 3) & 1) * 8 + (lane & 7);
    const uint32_t vb_coladd = (lane >> 4) * 8;

    for (int kt = 0; kt < ktiles; kt++) {
        const int st = kt & 1;
        if (kt + 1 < ktiles) { issue_kv(kt + 1, st ^ 1); CP_WAIT(1); }
        else                 { CP_WAIT(0); }
        __syncthreads();

        const uint32_t khb = F_KV0 + st * F_KVSZ;
        const uint32_t vhb = khb + V_OFF;

        // ---- S = Q K^T (single fp16) ----
        float c[8][4];
        #pragma unroll
        for (int t = 0; t < 8; t++)
            #pragma unroll
            for (int e = 0; e < 4; e++) c[t][e] = 0.f;

        #pragma unroll
        for (int kc = 0; kc < 8; kc++) {
            uint32_t a0, a1, a2, a3;
            LDMX4(a0, a1, a2, a3, qa_base + kc * 32);
            #pragma unroll
            for (int tp = 0; tp < 4; tp++) {
                uint32_t b0, b1, b2, b3;
                uint32_t kaddr = sb +
                    (khb + (tp * 16 + kb_row) * FSTR + kc * 16 + kb_coladd) * 2;
                LDMX4(b0, b1, b2, b3, kaddr);
                MMAH(c[2*tp],   a0, a1, a2, a3, b0, b1);
                MMAH(c[2*tp+1], a0, a1, a2, a3, b2, b3);
            }
        }

        // ---- causal mask on diagonal tiles ----
        const int rowg0 = q0 + w * 16 + (lane >> 2);
        if (kt >= 2 * qt) {
            const int k0 = kt * 64;
            #pragma unroll
            for (int t = 0; t < 8; t++) {
                int colb = k0 + t * 8 + (lane & 3) * 2;
                if (colb     > rowg0)     c[t][0] = -1e30f;
                if (colb + 1 > rowg0)     c[t][1] = -1e30f;
                if (colb     > rowg0 + 8) c[t][2] = -1e30f;
                if (colb + 1 > rowg0 + 8) c[t][3] = -1e30f;
            }
        }

        // ---- online softmax ----
        float mx0 = -1e30f, mx1 = -1e30f;
        #pragma unroll
        for (int t = 0; t < 8; t++) {
            mx0 = fmaxf(mx0, fmaxf(c[t][0], c[t][1]));
            mx1 = fmaxf(mx1, fmaxf(c[t][2], c[t][3]));
        }
        mx0 = fmaxf(mx0, __shfl_xor_sync(0xffffffffu, mx0, 1));
        mx0 = fmaxf(mx0, __shfl_xor_sync(0xffffffffu, mx0, 2));
        mx1 = fmaxf(mx1, __shfl_xor_sync(0xffffffffu, mx1, 1));
        mx1 = fmaxf(mx1, __shfl_xor_sync(0xffffffffu, mx1, 2));
        const float mn0 = fmaxf(m0, mx0);
        const float mn1 = fmaxf(m1, mx1);
        const float sc0 = __expf(m0 - mn0);
        const float sc1 = __expf(m1 - mn1);
        float sum0 = 0.f, sum1 = 0.f;
        #pragma unroll
        for (int t = 0; t < 8; t++) {
            c[t][0] = __expf(c[t][0] - mn0); sum0 += c[t][0];
            c[t][1] = __expf(c[t][1] - mn0); sum0 += c[t][1];
            c[t][2] = __expf(c[t][2] - mn1); sum1 += c[t][2];
            c[t][3] = __expf(c[t][3] - mn1); sum1 += c[t][3];
        }
        sum0 += __shfl_xor_sync(0xffffffffu, sum0, 1);
        sum0 += __shfl_xor_sync(0xffffffffu, sum0, 2);
        sum1 += __shfl_xor_sync(0xffffffffu, sum1, 1);
        sum1 += __shfl_xor_sync(0xffffffffu, sum1, 2);
        m0 = mn0; m1 = mn1;
        l0 = l0 * sc0 + sum0;
        l1 = l1 * sc1 + sum1;
        #pragma unroll
        for (int t = 0; t < 16; t++) {
            o[t][0] *= sc0; o[t][1] *= sc0;
            o[t][2] *= sc1; o[t][3] *= sc1;
        }

        // ---- O += P V  (P single fp16, V single fp16) ----
        #pragma unroll
        for (int kc = 0; kc < 4; kc++) {
            uint32_t pa[4];
            #pragma unroll
            for (int half = 0; half < 2; half++) {
                const int t = 2 * kc + half;
                pa[2*half]   = pack_h2f(c[t][0], c[t][1]);
                pa[2*half+1] = pack_h2f(c[t][2], c[t][3]);
            }
            #pragma unroll
            for (int tp = 0; tp < 8; tp++) {
                uint32_t v0, v1, v2, v3;
                uint32_t vaddr = sb +
                    (vhb + (kc * 16 + vb_rowadd) * FSTR + tp * 16 + vb_coladd) * 2;
                LDMX4T(v0, v1, v2, v3, vaddr);
                MMAH(o[2*tp],   pa[0], pa[1], pa[2], pa[3], v0, v1);
                MMAH(o[2*tp+1], pa[0], pa[1], pa[2], pa[3], v2, v3);
            }
        }
        __syncthreads();
    }

    // ---- normalize + 2-term fp16 store ----
    const float inv0 = 1.0f / l0;
    const float inv1 = 1.0f / l1;
    const int rowg = q0 + w * 16 + (lane >> 2);
    #pragma unroll
    for (int t = 0; t < 16; t++) {
        size_t g0 = ((size_t)(b * S_LEN + rowg)) * DM + head + t * 8 + (lane & 3) * 2;
        size_t g1 = g0 + 8 * DM;
        hf h0, l0b, h1, l1b;
        split1h(o[t][0] * inv0, h0, l0b);
        split1h(o[t][1] * inv0, h1, l1b);
        *(uint32_t*)(Oh + g0) = pack_h2(h0, h1);
        *(uint32_t*)(Ol + g0) = pack_h2(l0b, l1b);
        split1h(o[t][2] * inv1, h0, l0b);
        split1h(o[t][3] * inv1, h1, l1b);
        *(uint32_t*)(Oh + g1) = pack_h2(h0, h1);
        *(uint32_t*)(Ol + g1) = pack_h2(l0b, l1b);
    }
}

// ---------------------------------------------------------------------------
extern "C" void kernel_launch(void* const* d_in, const int* in_sizes, int n_in,
                              void* d_out, int out_size)
{
    const float* x  = (const float*)d_in[0];
    const float* wq = (const float*)d_in[1];
    const float* wk = (const float*)d_in[2];
    const float* wv = (const float*)d_in[3];
    const float* wo = (const float*)d_in[4];
    float* out = (float*)d_out;

    hf *xh, *qh, *kh, *vh, *ah, *al, *wh;
    cudaGetSymbolAddress((void**)&xh, g_xh);
    cudaGetSymbolAddress((void**)&qh, g_qh);
    cudaGetSymbolAddress((void**)&kh, g_kh);
    cudaGetSymbolAddress((void**)&vh, g_vh);
    cudaGetSymbolAddress((void**)&ah, g_ah);
    cudaGetSymbolAddress((void**)&al, g_al);
    cudaGetSymbolAddress((void**)&wh, g_wh);
    const size_t WSZ = (size_t)DM * DM;

    convert_x<<<(M_TOT * (size_t)DM) / (256 * 8), 256>>>(x, xh);
    dim3 tgrid(DM / 32, DM / 32), tblk(32, 8);
    transpose_convert<<<tgrid, tblk>>>(wq, wh + 0 * WSZ);
    transpose_convert<<<tgrid, tblk>>>(wk, wh + 1 * WSZ);
    transpose_convert<<<tgrid, tblk>>>(wv, wh + 2 * WSZ);
    transpose_convert<<<tgrid, tblk>>>(wo, wh + 3 * WSZ);

    cudaFuncSetAttribute(gemm_1t<1>, cudaFuncAttributeMaxDynamicSharedMemorySize,
                         GEMM1_SMEM);
    cudaFuncSetAttribute(gemm_1t<2>, cudaFuncAttributeMaxDynamicSharedMemorySize,
                         GEMM1_SMEM);
    cudaFuncSetAttribute(gemm_1t<3>, cudaFuncAttributeMaxDynamicSharedMemorySize,
                         GEMM1_SMEM);
    cudaFuncSetAttribute(gemm_2t, cudaFuncAttributeMaxDynamicSharedMemorySize,
                         GEMM2_SMEM);
    dim3 ggrid(DM / 128, M_TOT / 128);
    // q: RoPE + 1/sqrt(H) fused into epilogue; k: RoPE fused; v: plain fp16
    gemm_1t<2><<<ggrid, 256, GEMM1_SMEM>>>(xh, wh + 0 * WSZ, qh, M_TOT, DM, DM);
    gemm_1t<3><<<ggrid, 256, GEMM1_SMEM>>>(xh, wh + 1 * WSZ, kh, M_TOT, DM, DM);
    gemm_1t<1><<<ggrid, 256, GEMM1_SMEM>>>(xh, wh + 2 * WSZ, vh, M_TOT, DM, DM);

    cudaFuncSetAttribute(flash_tc4, cudaFuncAttributeMaxDynamicSharedMemorySize,
                         FLASH_SMEM_BYTES);
    dim3 fgrid(S_LEN / 128, NH, B_SZ);
    flash_tc4<<<fgrid, 256, FLASH_SMEM_BYTES>>>(qh, kh, vh, ah, al);

    gemm_2t<<<ggrid, 256, GEMM2_SMEM>>>(ah, al, wh + 3 * WSZ, out, M_TOT, DM, DM);
}

// round 10
// speedup vs baseline: 2.7934x; 1.1435x over previous
#include <cuda_runtime.h>
#include <cuda_fp16.h>
#include <cstdint>
#include <math.h>

#define B_SZ   4
#define S_LEN  2048
#define NH     16
#define HD     128
#define DM     2048
#define M_TOT  (B_SZ * S_LEN)
typedef __half hf;

// ---------------- scratch (device globals; allocation-free) ----------------
__device__ __align__(128) hf g_xh[(size_t)M_TOT * DM];
__device__ __align__(128) hf g_qh[(size_t)M_TOT * DM];
__device__ __align__(128) hf g_kh[(size_t)M_TOT * DM];
__device__ __align__(128) hf g_vh[(size_t)M_TOT * DM];
__device__ __align__(128) hf g_ah[(size_t)M_TOT * DM];
__device__ __align__(128) hf g_wh[4][(size_t)DM * DM];

// ---------------- helpers ----------------
__device__ __forceinline__ uint32_t smem_u32(const void* p) {
    uint32_t a;
    asm("{ .reg .u64 t; cvta.to.shared.u64 t, %1; cvt.u32.u64 %0, t; }"
        : "=r"(a) : "l"(p));
    return a;
}
__device__ __forceinline__ uint32_t pack_h2f(float a, float b) {
    __half2 t = __floats2half2_rn(a, b);
    return *reinterpret_cast<uint32_t*>(&t);
}

#define MMAH(d, a0, a1, a2, a3, b0, b1)                                      \
    asm volatile(                                                            \
        "mma.sync.aligned.m16n8k16.row.col.f32.f16.f16.f32 "                 \
        "{%0,%1,%2,%3}, {%4,%5,%6,%7}, {%8,%9}, {%0,%1,%2,%3};"              \
        : "+f"((d)[0]), "+f"((d)[1]), "+f"((d)[2]), "+f"((d)[3])             \
        : "r"(a0), "r"(a1), "r"(a2), "r"(a3), "r"(b0), "r"(b1))

#define LDMX4(r0, r1, r2, r3, addr)                                          \
    asm volatile("ldmatrix.sync.aligned.m8n8.x4.shared.b16 "                 \
        "{%0,%1,%2,%3}, [%4];"                                               \
        : "=r"(r0), "=r"(r1), "=r"(r2), "=r"(r3) : "r"(addr))

#define LDMX4T(r0, r1, r2, r3, addr)                                         \
    asm volatile("ldmatrix.sync.aligned.m8n8.x4.trans.shared.b16 "           \
        "{%0,%1,%2,%3}, [%4];"                                               \
        : "=r"(r0), "=r"(r1), "=r"(r2), "=r"(r3) : "r"(addr))

#define CP16(dst, src)                                                       \
    asm volatile("cp.async.cg.shared.global [%0], [%1], 16;"                 \
                 :: "r"(dst), "l"(src))
#define CP_COMMIT() asm volatile("cp.async.commit_group;" ::)
#define CP_WAIT(n)  asm volatile("cp.async.wait_group %0;" :: "n"(n))

// ---------------------------------------------------------------------------
// x: fp32 -> single fp16
// ---------------------------------------------------------------------------
__global__ __launch_bounds__(256) void convert_x(
    const float* __restrict__ in, hf* __restrict__ H)
{
    size_t base = ((size_t)blockIdx.x * 256 + threadIdx.x) * 8;
    float4 v0 = *(const float4*)(in + base);
    float4 v1 = *(const float4*)(in + base + 4);
    uint4 hv;
    hv.x = pack_h2f(v0.x, v0.y); hv.y = pack_h2f(v0.z, v0.w);
    hv.z = pack_h2f(v1.x, v1.y); hv.w = pack_h2f(v1.z, v1.w);
    *(uint4*)(H + base) = hv;
}

// ---------------------------------------------------------------------------
// w [K,N] fp32 -> [N,K] single fp16
// ---------------------------------------------------------------------------
__global__ __launch_bounds__(256) void transpose_convert(
    const float* __restrict__ in, hf* __restrict__ H)
{
    __shared__ float t[32][33];
    int x = blockIdx.x * 32 + threadIdx.x;
    int y = blockIdx.y * 32 + threadIdx.y;
    #pragma unroll
    for (int i = 0; i < 4; i++)
        t[threadIdx.y + i * 8][threadIdx.x] = in[(size_t)(y + i * 8) * DM + x];
    __syncthreads();
    x = blockIdx.y * 32 + threadIdx.x;
    y = blockIdx.x * 32 + threadIdx.y;
    #pragma unroll
    for (int i = 0; i < 4; i++)
        H[(size_t)(y + i * 8) * DM + x] =
            __float2half_rn(t[threadIdx.x][threadIdx.y + i * 8]);
}

// ---------------------------------------------------------------------------
// GEMM-1term: C = A * B^T, A/B single fp16, 1 MMA per position.
// 128x128 tile, 256 thr (8 warps 2x4), K-chunk 32, 3-stage cp.async.
// EPI: 0 = fp32 out; 1 = fp16 out; 2 = RoPE+qscale fp16 (q); 3 = RoPE fp16 (k)
// ---------------------------------------------------------------------------
#define GSTR   40
#define GA_EL  (128 * GSTR)
#define G1_STAGE_BYTES (2 * GA_EL * 2)          // 20480
#define GEMM1_SMEM (3 * G1_STAGE_BYTES)         // 61440

__device__ __forceinline__ void rope_pair(
    int row, int col, float& v0, float& v1, float scale)
{
    int s = row & (S_LEN - 1);
    int i = (col & (HD - 1)) >> 1;
    float fraction  = (2.0f * (float)i) / (float)HD;
    float timescale = exp2f(fraction * 13.287712379549449f); // log2(10000)
    float ang = (float)s / timescale;
    float sv, cv;
    sincosf(ang, &sv, &cv);
    float r0 = (v0 * cv - v1 * sv) * scale;
    float r1 = (v1 * cv + v0 * sv) * scale;
    v0 = r0; v1 = r1;
}

template<int EPI>
__global__ __launch_bounds__(256, 2) void gemm_1t(
    const hf* __restrict__ A, const hf* __restrict__ B,
    hf* __restrict__ Ch, float* __restrict__ Cf, int M, int N, int K)
{
    extern __shared__ __align__(16) char gsm[];
    const uint32_t sb = smem_u32(gsm);

    const int tid  = threadIdx.x;
    const int lane = tid & 31;
    const int wid  = tid >> 5;
    const int warpM = wid & 1;
    const int warpN = wid >> 1;
    const int n0 = blockIdx.x * 128;
    const int m0 = blockIdx.y * 128;

    const int lm = lane & 15, lh = lane >> 4;
    const int kb_row    = (lane >> 4) * 8 + (lane & 7);
    const int kb_coladd = ((lane >> 3) & 1) * 8;

    float acc[4][4][4];
    #pragma unroll
    for (int mt = 0; mt < 4; mt++)
        #pragma unroll
        for (int nt = 0; nt < 4; nt++)
            #pragma unroll
            for (int e = 0; e < 4; e++) acc[mt][nt][e] = 0.f;

    const int NK = K / 32;

    auto issue_stage = [&](int kt) {
        const uint32_t sbase = sb + (uint32_t)(kt % 3) * G1_STAGE_BYTES;
        #pragma unroll
        for (int j = 0; j < 2; j++) {
            int idx = tid * 2 + j;
            int row = idx >> 2, ch = idx & 3;
            uint32_t doff = (uint32_t)(row * GSTR + ch * 8) * 2;
            CP16(sbase + doff,             A + (size_t)(m0 + row) * K + kt * 32 + ch * 8);
            CP16(sbase + GA_EL * 2 + doff, B + (size_t)(n0 + row) * K + kt * 32 + ch * 8);
        }
        CP_COMMIT();
    };

    issue_stage(0);
    issue_stage(1);

    for (int kt = 0; kt < NK; kt++) {
        if (kt + 1 < NK) CP_WAIT(1); else CP_WAIT(0);
        __syncthreads();
        if (kt + 2 < NK) issue_stage(kt + 2);

        const uint32_t sbase = sb + (uint32_t)(kt % 3) * G1_STAGE_BYTES;
        #pragma unroll
        for (int kc = 0; kc < 2; kc++) {
            uint32_t ah[4][4], bh[2][4];
            #pragma unroll
            for (int mt = 0; mt < 4; mt++) {
                uint32_t aaddr = sbase +
                    (uint32_t)((warpM * 64 + mt * 16 + lm) * GSTR + kc * 16 + lh * 8) * 2;
                LDMX4(ah[mt][0], ah[mt][1], ah[mt][2], ah[mt][3], aaddr);
            }
            #pragma unroll
            for (int ng = 0; ng < 2; ng++) {
                uint32_t baddr = sbase + GA_EL * 2 +
                    (uint32_t)((warpN * 32 + ng * 16 + kb_row) * GSTR + kc * 16 + kb_coladd) * 2;
                LDMX4(bh[ng][0], bh[ng][1], bh[ng][2], bh[ng][3], baddr);
            }
            #pragma unroll
            for (int mt = 0; mt < 4; mt++)
                #pragma unroll
                for (int nt = 0; nt < 4; nt++) {
                    const int ng = nt >> 1, o = (nt & 1) * 2;
                    MMAH(acc[mt][nt], ah[mt][0], ah[mt][1], ah[mt][2], ah[mt][3],
                         bh[ng][o], bh[ng][o + 1]);
                }
        }
        __syncthreads();
    }

    const int mrow = lane >> 2;
    const int kcol = (lane & 3) * 2;    // even -> (col, col+1) is a RoPE pair
    const float qs = (EPI == 2) ? 0.08838834764831845f : 1.0f;
    #pragma unroll
    for (int mt = 0; mt < 4; mt++) {
        #pragma unroll
        for (int nt = 0; nt < 4; nt++) {
            int row = m0 + warpM * 64 + mt * 16 + mrow;
            int col = n0 + warpN * 32 + nt * 8 + kcol;
            float v0 = acc[mt][nt][0], v1 = acc[mt][nt][1];
            float v2 = acc[mt][nt][2], v3 = acc[mt][nt][3];
            if (EPI >= 2) {
                rope_pair(row,     col, v0, v1, qs);
                rope_pair(row + 8, col, v2, v3, qs);
            }
            if (EPI == 0) {
                *(float2*)(Cf + (size_t)row * N + col)       = make_float2(v0, v1);
                *(float2*)(Cf + (size_t)(row + 8) * N + col) = make_float2(v2, v3);
            } else {
                *(uint32_t*)(Ch + (size_t)row * N + col)       = pack_h2f(v0, v1);
                *(uint32_t*)(Ch + (size_t)(row + 8) * N + col) = pack_h2f(v2, v3);
            }
        }
    }
}

// ---------------------------------------------------------------------------
// Flash attention: Q,K,V single fp16 (1 MMA per fragment in QK and PV).
// CTA: (128-row q tile, head, batch), 8 warps, double-buffered K/V cp.async.
// Output: single fp16 attn.
// ---------------------------------------------------------------------------
#define FSTR    136
#define F_Q     0
#define F_KV0   (128 * FSTR)
#define F_KVSZ  (2 * 64 * FSTR)
#define V_OFF   (64 * FSTR)
#define FLASH_SMEM_BYTES ((F_KV0 + 2 * F_KVSZ) * 2)   // 104448

__global__ __launch_bounds__(256, 1) void flash_tc5(
    const hf* __restrict__ Qh, const hf* __restrict__ Kh,
    const hf* __restrict__ Vh, hf* __restrict__ Oh)
{
    extern __shared__ __align__(16) char fsm[];
    const uint32_t sb = smem_u32(fsm);

    const int tid  = threadIdx.x;
    const int lane = tid & 31;
    const int w    = tid >> 5;
    const int qt   = blockIdx.x;
    const int hN   = blockIdx.y;
    const int b    = blockIdx.z;
    const int q0   = qt * 128;
    const size_t head = (size_t)hN * HD;

    auto issue_kv = [&](int kt, int st) {
        const int k0 = kt * 64;
        const uint32_t base = sb + (F_KV0 + st * F_KVSZ) * 2;
        #pragma unroll
        for (int i = 0; i < 4; i++) {
            int idx = tid + i * 256;            // 0..1023
            int row = idx >> 4, ch = idx & 15;
            uint32_t doff = (uint32_t)(row * FSTR + ch * 8) * 2;
            size_t g = ((size_t)(b * S_LEN + k0 + row)) * DM + head + ch * 8;
            CP16(base + doff,             Kh + g);
            CP16(base + V_OFF * 2 + doff, Vh + g);
        }
        CP_COMMIT();
    };

    #pragma unroll
    for (int i = 0; i < 8; i++) {
        int idx = tid + i * 256;                // 0..2047
        int row = idx >> 4, ch = idx & 15;
        uint32_t doff = (uint32_t)(row * FSTR + ch * 8) * 2;
        size_t g = ((size_t)(b * S_LEN + q0 + row)) * DM + head + ch * 8;
        CP16(sb + doff, Qh + g);
    }
    issue_kv(0, 0);

    float m0 = -1e30f, m1 = -1e30f, l0 = 0.f, l1 = 0.f;
    float o[16][4];
    #pragma unroll
    for (int t = 0; t < 16; t++)
        #pragma unroll
        for (int e = 0; e < 4; e++) o[t][e] = 0.f;

    const int ktiles = 2 * qt + 2;

    const uint32_t qa_base =
        sb + ((w * 16 + (lane & 15)) * FSTR + (lane >> 4) * 8) * 2;
    const uint32_t kb_row    = (lane >> 4) * 8 + (lane & 7);
    const uint32_t kb_coladd = ((lane >> 3) & 1) * 8;
    const uint32_t vb_rowadd = ((lane >> 3) & 1) * 8 + (lane & 7);
    const uint32_t vb_coladd = (lane >> 4) * 8;

    for (int kt = 0; kt < ktiles; kt++) {
        const int st = kt & 1;
        if (kt + 1 < ktiles) { issue_kv(kt + 1, st ^ 1); CP_WAIT(1); }
        else                 { CP_WAIT(0); }
        __syncthreads();

        const uint32_t khb = F_KV0 + st * F_KVSZ;
        const uint32_t vhb = khb + V_OFF;

        // ---- S = Q K^T ----
        float c[8][4];
        #pragma unroll
        for (int t = 0; t < 8; t++)
            #pragma unroll
            for (int e = 0; e < 4; e++) c[t][e] = 0.f;

        #pragma unroll
        for (int kc = 0; kc < 8; kc++) {
            uint32_t a0, a1, a2, a3;
            LDMX4(a0, a1, a2, a3, qa_base + kc * 32);
            #pragma unroll
            for (int tp = 0; tp < 4; tp++) {
                uint32_t b0, b1, b2, b3;
                uint32_t kaddr = sb +
                    (khb + (tp * 16 + kb_row) * FSTR + kc * 16 + kb_coladd) * 2;
                LDMX4(b0, b1, b2, b3, kaddr);
                MMAH(c[2*tp],   a0, a1, a2, a3, b0, b1);
                MMAH(c[2*tp+1], a0, a1, a2, a3, b2, b3);
            }
        }

        // ---- causal mask on diagonal tiles ----
        const int rowg0 = q0 + w * 16 + (lane >> 2);
        if (kt >= 2 * qt) {
            const int k0 = kt * 64;
            #pragma unroll
            for (int t = 0; t < 8; t++) {
                int colb = k0 + t * 8 + (lane & 3) * 2;
                if (colb     > rowg0)     c[t][0] = -1e30f;
                if (colb + 1 > rowg0)     c[t][1] = -1e30f;
                if (colb     > rowg0 + 8) c[t][2] = -1e30f;
                if (colb + 1 > rowg0 + 8) c[t][3] = -1e30f;
            }
        }

        // ---- online softmax ----
        float mx0 = -1e30f, mx1 = -1e30f;
        #pragma unroll
        for (int t = 0; t < 8; t++) {
            mx0 = fmaxf(mx0, fmaxf(c[t][0], c[t][1]));
            mx1 = fmaxf(mx1, fmaxf(c[t][2], c[t][3]));
        }
        mx0 = fmaxf(mx0, __shfl_xor_sync(0xffffffffu, mx0, 1));
        mx0 = fmaxf(mx0, __shfl_xor_sync(0xffffffffu, mx0, 2));
        mx1 = fmaxf(mx1, __shfl_xor_sync(0xffffffffu, mx1, 1));
        mx1 = fmaxf(mx1, __shfl_xor_sync(0xffffffffu, mx1, 2));
        const float mn0 = fmaxf(m0, mx0);
        const float mn1 = fmaxf(m1, mx1);
        const float sc0 = __expf(m0 - mn0);
        const float sc1 = __expf(m1 - mn1);
        float sum0 = 0.f, sum1 = 0.f;
        #pragma unroll
        for (int t = 0; t < 8; t++) {
            c[t][0] = __expf(c[t][0] - mn0); sum0 += c[t][0];
            c[t][1] = __expf(c[t][1] - mn0); sum0 += c[t][1];
            c[t][2] = __expf(c[t][2] - mn1); sum1 += c[t][2];
            c[t][3] = __expf(c[t][3] - mn1); sum1 += c[t][3];
        }
        sum0 += __shfl_xor_sync(0xffffffffu, sum0, 1);
        sum0 += __shfl_xor_sync(0xffffffffu, sum0, 2);
        sum1 += __shfl_xor_sync(0xffffffffu, sum1, 1);
        sum1 += __shfl_xor_sync(0xffffffffu, sum1, 2);
        m0 = mn0; m1 = mn1;
        l0 = l0 * sc0 + sum0;
        l1 = l1 * sc1 + sum1;
        #pragma unroll
        for (int t = 0; t < 16; t++) {
            o[t][0] *= sc0; o[t][1] *= sc0;
            o[t][2] *= sc1; o[t][3] *= sc1;
        }

        // ---- O += P V ----
        #pragma unroll
        for (int kc = 0; kc < 4; kc++) {
            uint32_t pa[4];
            #pragma unroll
            for (int half = 0; half < 2; half++) {
                const int t = 2 * kc + half;
                pa[2*half]   = pack_h2f(c[t][0], c[t][1]);
                pa[2*half+1] = pack_h2f(c[t][2], c[t][3]);
            }
            #pragma unroll
            for (int tp = 0; tp < 8; tp++) {
                uint32_t v0, v1, v2, v3;
                uint32_t vaddr = sb +
                    (vhb + (kc * 16 + vb_rowadd) * FSTR + tp * 16 + vb_coladd) * 2;
                LDMX4T(v0, v1, v2, v3, vaddr);
                MMAH(o[2*tp],   pa[0], pa[1], pa[2], pa[3], v0, v1);
                MMAH(o[2*tp+1], pa[0], pa[1], pa[2], pa[3], v2, v3);
            }
        }
        __syncthreads();
    }

    // ---- normalize + single fp16 store ----
    const float inv0 = 1.0f / l0;
    const float inv1 = 1.0f / l1;
    const int rowg = q0 + w * 16 + (lane >> 2);
    #pragma unroll
    for (int t = 0; t < 16; t++) {
        size_t g0 = ((size_t)(b * S_LEN + rowg)) * DM + head + t * 8 + (lane & 3) * 2;
        size_t g1 = g0 + 8 * DM;
        *(uint32_t*)(Oh + g0) = pack_h2f(o[t][0] * inv0, o[t][1] * inv0);
        *(uint32_t*)(Oh + g1) = pack_h2f(o[t][2] * inv1, o[t][3] * inv1);
    }
}

// ---------------------------------------------------------------------------
extern "C" void kernel_launch(void* const* d_in, const int* in_sizes, int n_in,
                              void* d_out, int out_size)
{
    const float* x  = (const float*)d_in[0];
    const float* wq = (const float*)d_in[1];
    const float* wk = (const float*)d_in[2];
    const float* wv = (const float*)d_in[3];
    const float* wo = (const float*)d_in[4];
    float* out = (float*)d_out;

    hf *xh, *qh, *kh, *vh, *ah, *wh;
    cudaGetSymbolAddress((void**)&xh, g_xh);
    cudaGetSymbolAddress((void**)&qh, g_qh);
    cudaGetSymbolAddress((void**)&kh, g_kh);
    cudaGetSymbolAddress((void**)&vh, g_vh);
    cudaGetSymbolAddress((void**)&ah, g_ah);
    cudaGetSymbolAddress((void**)&wh, g_wh);
    const size_t WSZ = (size_t)DM * DM;

    convert_x<<<(M_TOT * (size_t)DM) / (256 * 8), 256>>>(x, xh);
    dim3 tgrid(DM / 32, DM / 32), tblk(32, 8);
    transpose_convert<<<tgrid, tblk>>>(wq, wh + 0 * WSZ);
    transpose_convert<<<tgrid, tblk>>>(wk, wh + 1 * WSZ);
    transpose_convert<<<tgrid, tblk>>>(wv, wh + 2 * WSZ);
    transpose_convert<<<tgrid, tblk>>>(wo, wh + 3 * WSZ);

    cudaFuncSetAttribute(gemm_1t<0>, cudaFuncAttributeMaxDynamicSharedMemorySize,
                         GEMM1_SMEM);
    cudaFuncSetAttribute(gemm_1t<1>, cudaFuncAttributeMaxDynamicSharedMemorySize,
                         GEMM1_SMEM);
    cudaFuncSetAttribute(gemm_1t<2>, cudaFuncAttributeMaxDynamicSharedMemorySize,
                         GEMM1_SMEM);
    cudaFuncSetAttribute(gemm_1t<3>, cudaFuncAttributeMaxDynamicSharedMemorySize,
                         GEMM1_SMEM);
    dim3 ggrid(DM / 128, M_TOT / 128);
    // q: RoPE + 1/sqrt(H) fused; k: RoPE fused; v: plain fp16
    gemm_1t<2><<<ggrid, 256, GEMM1_SMEM>>>(xh, wh + 0 * WSZ, qh, nullptr, M_TOT, DM, DM);
    gemm_1t<3><<<ggrid, 256, GEMM1_SMEM>>>(xh, wh + 1 * WSZ, kh, nullptr, M_TOT, DM, DM);
    gemm_1t<1><<<ggrid, 256, GEMM1_SMEM>>>(xh, wh + 2 * WSZ, vh, nullptr, M_TOT, DM, DM);

    cudaFuncSetAttribute(flash_tc5, cudaFuncAttributeMaxDynamicSharedMemorySize,
                         FLASH_SMEM_BYTES);
    dim3 fgrid(S_LEN / 128, NH, B_SZ);
    flash_tc5<<<fgrid, 256, FLASH_SMEM_BYTES>>>(qh, kh, vh, ah);

    // out-proj: single fp16, fp32 output
    gemm_1t<0><<<ggrid, 256, GEMM1_SMEM>>>(ah, wh + 3 * WSZ, nullptr, out, M_TOT, DM, DM);
}

// round 12
// speedup vs baseline: 2.8820x; 1.0317x over previous
#include <cuda_runtime.h>
#include <cuda_fp16.h>
#include <cstdint>
#include <math.h>

#define B_SZ   4
#define S_LEN  2048
#define NH     16
#define HD     128
#define DM     2048
#define M_TOT  (B_SZ * S_LEN)
typedef __half hf;

// ---------------- scratch (device globals; allocation-free) ----------------
__device__ __align__(128) hf g_xh[(size_t)M_TOT * DM];
__device__ __align__(128) hf g_qh[(size_t)M_TOT * DM];
__device__ __align__(128) hf g_kh[(size_t)M_TOT * DM];
__device__ __align__(128) hf g_vh[(size_t)M_TOT * DM];
__device__ __align__(128) hf g_ah[(size_t)M_TOT * DM];
__device__ __align__(128) hf g_wh[4][(size_t)DM * DM];   // [wq;wk;wv;wo], [N,K] fp16

// ---------------- helpers ----------------
__device__ __forceinline__ uint32_t smem_u32(const void* p) {
    uint32_t a;
    asm("{ .reg .u64 t; cvta.to.shared.u64 t, %1; cvt.u32.u64 %0, t; }"
        : "=r"(a) : "l"(p));
    return a;
}
__device__ __forceinline__ uint32_t pack_h2f(float a, float b) {
    __half2 t = __floats2half2_rn(a, b);
    return *reinterpret_cast<uint32_t*>(&t);
}

#define MMAH(d, a0, a1, a2, a3, b0, b1)                                      \
    asm volatile(                                                            \
        "mma.sync.aligned.m16n8k16.row.col.f32.f16.f16.f32 "                 \
        "{%0,%1,%2,%3}, {%4,%5,%6,%7}, {%8,%9}, {%0,%1,%2,%3};"              \
        : "+f"((d)[0]), "+f"((d)[1]), "+f"((d)[2]), "+f"((d)[3])             \
        : "r"(a0), "r"(a1), "r"(a2), "r"(a3), "r"(b0), "r"(b1))

#define LDMX4(r0, r1, r2, r3, addr)                                          \
    asm volatile("ldmatrix.sync.aligned.m8n8.x4.shared.b16 "                 \
        "{%0,%1,%2,%3}, [%4];"                                               \
        : "=r"(r0), "=r"(r1), "=r"(r2), "=r"(r3) : "r"(addr))

#define LDMX4T(r0, r1, r2, r3, addr)                                         \
    asm volatile("ldmatrix.sync.aligned.m8n8.x4.trans.shared.b16 "           \
        "{%0,%1,%2,%3}, [%4];"                                               \
        : "=r"(r0), "=r"(r1), "=r"(r2), "=r"(r3) : "r"(addr))

#define CP16(dst, src)                                                       \
    asm volatile("cp.async.cg.shared.global [%0], [%1], 16;"                 \
                 :: "r"(dst), "l"(src))
#define CP_COMMIT() asm volatile("cp.async.commit_group;" ::)
#define CP_WAIT(n)  asm volatile("cp.async.wait_group %0;" :: "n"(n))

// ---------------------------------------------------------------------------
// x: fp32 -> single fp16
// ---------------------------------------------------------------------------
__global__ __launch_bounds__(256) void convert_x(
    const float* __restrict__ in, hf* __restrict__ H)
{
    size_t base = ((size_t)blockIdx.x * 256 + threadIdx.x) * 8;
    float4 v0 = *(const float4*)(in + base);
    float4 v1 = *(const float4*)(in + base + 4);
    uint4 hv;
    hv.x = pack_h2f(v0.x, v0.y); hv.y = pack_h2f(v0.z, v0.w);
    hv.z = pack_h2f(v1.x, v1.y); hv.w = pack_h2f(v1.z, v1.w);
    *(uint4*)(H + base) = hv;
}

// ---------------------------------------------------------------------------
// All 4 weights: [K,N] fp32 -> [N,K] fp16 in one launch (z = weight index)
// ---------------------------------------------------------------------------
__global__ __launch_bounds__(256) void transpose_convert4(
    const float* __restrict__ w0, const float* __restrict__ w1,
    const float* __restrict__ w2, const float* __restrict__ w3,
    hf* __restrict__ Hbase)
{
    __shared__ float t[32][33];
    const int z = blockIdx.z;
    const float* in = (z == 0) ? w0 : (z == 1) ? w1 : (z == 2) ? w2 : w3;
    hf* H = Hbase + (size_t)z * DM * DM;

    int x = blockIdx.x * 32 + threadIdx.x;
    int y = blockIdx.y * 32 + threadIdx.y;
    #pragma unroll
    for (int i = 0; i < 4; i++)
        t[threadIdx.y + i * 8][threadIdx.x] = in[(size_t)(y + i * 8) * DM + x];
    __syncthreads();
    x = blockIdx.y * 32 + threadIdx.x;
    y = blockIdx.x * 32 + threadIdx.y;
    #pragma unroll
    for (int i = 0; i < 4; i++)
        H[(size_t)(y + i * 8) * DM + x] =
            __float2half_rn(t[threadIdx.x][threadIdx.y + i * 8]);
}

// ---------------------------------------------------------------------------
// RoPE epilogue helper
// ---------------------------------------------------------------------------
__device__ __forceinline__ void rope_pair(
    int row, int col, float& v0, float& v1, float scale)
{
    int s = row & (S_LEN - 1);
    int i = (col & (HD - 1)) >> 1;
    float fraction  = (2.0f * (float)i) / (float)HD;
    float timescale = exp2f(fraction * 13.287712379549449f); // log2(10000)
    float ang = (float)s / timescale;
    float sv, cv;
    sincosf(ang, &sv, &cv);
    float r0 = (v0 * cv - v1 * sv) * scale;
    float r1 = (v1 * cv + v0 * sv) * scale;
    v0 = r0; v1 = r1;
}

// ---------------------------------------------------------------------------
// GEMM core: 128x128 tile, 256 thr (8 warps 2x4), K-chunk 32, 3-stage cp.async.
// Single fp16 operands, 1 MMA per position, ONE sync per k-chunk.
// Pipeline invariant: prologue issues groups {0,1}; each iter issues kt+2
// AFTER the sync, so 2 groups are pending at each WAIT(1).
// FUSED=1: B is [3*DM, DM] stacked qkv weights; epilogue routes to q/k/v with
//          RoPE (+1/sqrt(H) for q). FUSED=0: plain GEMM, fp32 out (out-proj).
// ---------------------------------------------------------------------------
#define GSTR   40
#define GA_EL  (128 * GSTR)
#define G1_STAGE_BYTES (2 * GA_EL * 2)          // 20480
#define GEMM1_SMEM (3 * G1_STAGE_BYTES)         // 61440

template<int FUSED>
__global__ __launch_bounds__(256, 2) void gemm_1t(
    const hf* __restrict__ A, const hf* __restrict__ B,
    hf* __restrict__ Q, hf* __restrict__ Kout, hf* __restrict__ V,
    float* __restrict__ Cf, int M, int K)
{
    extern __shared__ __align__(16) char gsm[];
    const uint32_t sb = smem_u32(gsm);

    const int tid  = threadIdx.x;
    const int lane = tid & 31;
    const int wid  = tid >> 5;
    const int warpM = wid & 1;
    const int warpN = wid >> 1;
    const int n0 = blockIdx.x * 128;
    const int m0 = blockIdx.y * 128;

    const int lm = lane & 15, lh = lane >> 4;
    const int kb_row    = (lane >> 4) * 8 + (lane & 7);
    const int kb_coladd = ((lane >> 3) & 1) * 8;

    float acc[4][4][4];
    #pragma unroll
    for (int mt = 0; mt < 4; mt++)
        #pragma unroll
        for (int nt = 0; nt < 4; nt++)
            #pragma unroll
            for (int e = 0; e < 4; e++) acc[mt][nt][e] = 0.f;

    const int NK = K / 32;

    auto issue_stage = [&](int kt) {
        const uint32_t sbase = sb + (uint32_t)(kt % 3) * G1_STAGE_BYTES;
        #pragma unroll
        for (int j = 0; j < 2; j++) {
            int idx = tid * 2 + j;
            int row = idx >> 2, ch = idx & 3;
            uint32_t doff = (uint32_t)(row * GSTR + ch * 8) * 2;
            CP16(sbase + doff,             A + (size_t)(m0 + row) * K + kt * 32 + ch * 8);
            CP16(sbase + GA_EL * 2 + doff, B + (size_t)(n0 + row) * K + kt * 32 + ch * 8);
        }
        CP_COMMIT();
    };

    issue_stage(0);
    issue_stage(1);

    for (int kt = 0; kt < NK; kt++) {
        if (kt + 1 < NK) CP_WAIT(1); else CP_WAIT(0);
        __syncthreads();                 // single barrier per chunk
        if (kt + 2 < NK) issue_stage(kt + 2);

        const uint32_t sbase = sb + (uint32_t)(kt % 3) * G1_STAGE_BYTES;
        #pragma unroll
        for (int kc = 0; kc < 2; kc++) {
            uint32_t ah[4][4], bh[2][4];
            #pragma unroll
            for (int mt = 0; mt < 4; mt++) {
                uint32_t aaddr = sbase +
                    (uint32_t)((warpM * 64 + mt * 16 + lm) * GSTR + kc * 16 + lh * 8) * 2;
                LDMX4(ah[mt][0], ah[mt][1], ah[mt][2], ah[mt][3], aaddr);
            }
            #pragma unroll
            for (int ng = 0; ng < 2; ng++) {
                uint32_t baddr = sbase + GA_EL * 2 +
                    (uint32_t)((warpN * 32 + ng * 16 + kb_row) * GSTR + kc * 16 + kb_coladd) * 2;
                LDMX4(bh[ng][0], bh[ng][1], bh[ng][2], bh[ng][3], baddr);
            }
            #pragma unroll
            for (int mt = 0; mt < 4; mt++)
                #pragma unroll
                for (int nt = 0; nt < 4; nt++) {
                    const int ng = nt >> 1, o = (nt & 1) * 2;
                    MMAH(acc[mt][nt], ah[mt][0], ah[mt][1], ah[mt][2], ah[mt][3],
                         bh[ng][o], bh[ng][o + 1]);
                }
        }
    }

    const int mrow = lane >> 2;
    const int kcol = (lane & 3) * 2;    // even -> (col, col+1) is a RoPE pair
    if (FUSED) {
        const int which = blockIdx.x >> 4;    // 0=q, 1=k, 2=v
        hf* Ch = (which == 0) ? Q : (which == 1) ? Kout : V;
        const float qs = (which == 0) ? 0.08838834764831845f : 1.0f;
        const bool rope = (which < 2);
        #pragma unroll
        for (int mt = 0; mt < 4; mt++) {
            #pragma unroll
            for (int nt = 0; nt < 4; nt++) {
                int row = m0 + warpM * 64 + mt * 16 + mrow;
                int col = n0 + warpN * 32 + nt * 8 + kcol;   // global; &127 ok per-head
                float v0 = acc[mt][nt][0], v1 = acc[mt][nt][1];
                float v2 = acc[mt][nt][2], v3 = acc[mt][nt][3];
                if (rope) {
                    rope_pair(row,     col, v0, v1, qs);
                    rope_pair(row + 8, col, v2, v3, qs);
                }
                int cl = col & (DM - 1);
                *(uint32_t*)(Ch + (size_t)row * DM + cl)       = pack_h2f(v0, v1);
                *(uint32_t*)(Ch + (size_t)(row + 8) * DM + cl) = pack_h2f(v2, v3);
            }
        }
    } else {
        #pragma unroll
        for (int mt = 0; mt < 4; mt++) {
            #pragma unroll
            for (int nt = 0; nt < 4; nt++) {
                int row = m0 + warpM * 64 + mt * 16 + mrow;
                int col = n0 + warpN * 32 + nt * 8 + kcol;
                *(float2*)(Cf + (size_t)row * DM + col) =
                    make_float2(acc[mt][nt][0], acc[mt][nt][1]);
                *(float2*)(Cf + (size_t)(row + 8) * DM + col) =
                    make_float2(acc[mt][nt][2], acc[mt][nt][3]);
            }
        }
    }
}

// ---------------------------------------------------------------------------
// Flash attention: Q,K,V single fp16, one sync per k-tile.
// Pipeline: issue-after-sync with CP_WAIT(0) — at each wait exactly one group
// (tile kt) is pending; tile kt+1's load overlaps tile kt's full compute.
// ---------------------------------------------------------------------------
#define FSTR    136
#define F_Q     0
#define F_KV0   (128 * FSTR)
#define F_KVSZ  (2 * 64 * FSTR)
#define V_OFF   (64 * FSTR)
#define FLASH_SMEM_BYTES ((F_KV0 + 2 * F_KVSZ) * 2)   // 104448

__global__ __launch_bounds__(256, 1) void flash_tc5(
    const hf* __restrict__ Qh, const hf* __restrict__ Kh,
    const hf* __restrict__ Vh, hf* __restrict__ Oh)
{
    extern __shared__ __align__(16) char fsm[];
    const uint32_t sb = smem_u32(fsm);

    const int tid  = threadIdx.x;
    const int lane = tid & 31;
    const int w    = tid >> 5;
    const int qt   = blockIdx.x;
    const int hN   = blockIdx.y;
    const int b    = blockIdx.z;
    const int q0   = qt * 128;
    const size_t head = (size_t)hN * HD;

    auto issue_kv = [&](int kt, int st) {
        const int k0 = kt * 64;
        const uint32_t base = sb + (F_KV0 + st * F_KVSZ) * 2;
        #pragma unroll
        for (int i = 0; i < 4; i++) {
            int idx = tid + i * 256;
            int row = idx >> 4, ch = idx & 15;
            uint32_t doff = (uint32_t)(row * FSTR + ch * 8) * 2;
            size_t g = ((size_t)(b * S_LEN + k0 + row)) * DM + head + ch * 8;
            CP16(base + doff,             Kh + g);
            CP16(base + V_OFF * 2 + doff, Vh + g);
        }
        CP_COMMIT();
    };

    #pragma unroll
    for (int i = 0; i < 8; i++) {
        int idx = tid + i * 256;
        int row = idx >> 4, ch = idx & 15;
        uint32_t doff = (uint32_t)(row * FSTR + ch * 8) * 2;
        size_t g = ((size_t)(b * S_LEN + q0 + row)) * DM + head + ch * 8;
        CP16(sb + doff, Qh + g);
    }
    issue_kv(0, 0);

    float m0 = -1e30f, m1 = -1e30f, l0 = 0.f, l1 = 0.f;
    float o[16][4];
    #pragma unroll
    for (int t = 0; t < 16; t++)
        #pragma unroll
        for (int e = 0; e < 4; e++) o[t][e] = 0.f;

    const int ktiles = 2 * qt + 2;

    const uint32_t qa_base =
        sb + ((w * 16 + (lane & 15)) * FSTR + (lane >> 4) * 8) * 2;
    const uint32_t kb_row    = (lane >> 4) * 8 + (lane & 7);
    const uint32_t kb_coladd = ((lane >> 3) & 1) * 8;
    const uint32_t vb_rowadd = ((lane >> 3) & 1) * 8 + (lane & 7);
    const uint32_t vb_coladd = (lane >> 4) * 8;

    for (int kt = 0; kt < ktiles; kt++) {
        const int st = kt & 1;
        CP_WAIT(0);                        // tile kt (and Q on kt=0) complete
        __syncthreads();                   // all warps done with buf st^1
        if (kt + 1 < ktiles) issue_kv(kt + 1, st ^ 1);

        const uint32_t khb = F_KV0 + st * F_KVSZ;
        const uint32_t vhb = khb + V_OFF;

        // ---- S = Q K^T ----
        float c[8][4];
        #pragma unroll
        for (int t = 0; t < 8; t++)
            #pragma unroll
            for (int e = 0; e < 4; e++) c[t][e] = 0.f;

        #pragma unroll
        for (int kc = 0; kc < 8; kc++) {
            uint32_t a0, a1, a2, a3;
            LDMX4(a0, a1, a2, a3, qa_base + kc * 32);
            #pragma unroll
            for (int tp = 0; tp < 4; tp++) {
                uint32_t b0, b1, b2, b3;
                uint32_t kaddr = sb +
                    (khb + (tp * 16 + kb_row) * FSTR + kc * 16 + kb_coladd) * 2;
                LDMX4(b0, b1, b2, b3, kaddr);
                MMAH(c[2*tp],   a0, a1, a2, a3, b0, b1);
                MMAH(c[2*tp+1], a0, a1, a2, a3, b2, b3);
            }
        }

        // ---- causal mask on diagonal tiles ----
        const int rowg0 = q0 + w * 16 + (lane >> 2);
        if (kt >= 2 * qt) {
            const int k0 = kt * 64;
            #pragma unroll
            for (int t = 0; t < 8; t++) {
                int colb = k0 + t * 8 + (lane & 3) * 2;
                if (colb     > rowg0)     c[t][0] = -1e30f;
                if (colb + 1 > rowg0)     c[t][1] = -1e30f;
                if (colb     > rowg0 + 8) c[t][2] = -1e30f;
                if (colb + 1 > rowg0 + 8) c[t][3] = -1e30f;
            }
        }

        // ---- online softmax ----
        float mx0 = -1e30f, mx1 = -1e30f;
        #pragma unroll
        for (int t = 0; t < 8; t++) {
            mx0 = fmaxf(mx0, fmaxf(c[t][0], c[t][1]));
            mx1 = fmaxf(mx1, fmaxf(c[t][2], c[t][3]));
        }
        mx0 = fmaxf(mx0, __shfl_xor_sync(0xffffffffu, mx0, 1));
        mx0 = fmaxf(mx0, __shfl_xor_sync(0xffffffffu, mx0, 2));
        mx1 = fmaxf(mx1, __shfl_xor_sync(0xffffffffu, mx1, 1));
        mx1 = fmaxf(mx1, __shfl_xor_sync(0xffffffffu, mx1, 2));
        const float mn0 = fmaxf(m0, mx0);
        const float mn1 = fmaxf(m1, mx1);
        const float sc0 = __expf(m0 - mn0);
        const float sc1 = __expf(m1 - mn1);
        float sum0 = 0.f, sum1 = 0.f;
        #pragma unroll
        for (int t = 0; t < 8; t++) {
            c[t][0] = __expf(c[t][0] - mn0); sum0 += c[t][0];
            c[t][1] = __expf(c[t][1] - mn0); sum0 += c[t][1];
            c[t][2] = __expf(c[t][2] - mn1); sum1 += c[t][2];
            c[t][3] = __expf(c[t][3] - mn1); sum1 += c[t][3];
        }
        sum0 += __shfl_xor_sync(0xffffffffu, sum0, 1);
        sum0 += __shfl_xor_sync(0xffffffffu, sum0, 2);
        sum1 += __shfl_xor_sync(0xffffffffu, sum1, 1);
        sum1 += __shfl_xor_sync(0xffffffffu, sum1, 2);
        m0 = mn0; m1 = mn1;
        l0 = l0 * sc0 + sum0;
        l1 = l1 * sc1 + sum1;
        #pragma unroll
        for (int t = 0; t < 16; t++) {
            o[t][0] *= sc0; o[t][1] *= sc0;
            o[t][2] *= sc1; o[t][3] *= sc1;
        }

        // ---- O += P V ----
        #pragma unroll
        for (int kc = 0; kc < 4; kc++) {
            uint32_t pa[4];
            #pragma unroll
            for (int half = 0; half < 2; half++) {
                const int t = 2 * kc + half;
                pa[2*half]   = pack_h2f(c[t][0], c[t][1]);
                pa[2*half+1] = pack_h2f(c[t][2], c[t][3]);
            }
            #pragma unroll
            for (int tp = 0; tp < 8; tp++) {
                uint32_t v0, v1, v2, v3;
                uint32_t vaddr = sb +
                    (vhb + (kc * 16 + vb_rowadd) * FSTR + tp * 16 + vb_coladd) * 2;
                LDMX4T(v0, v1, v2, v3, vaddr);
                MMAH(o[2*tp],   pa[0], pa[1], pa[2], pa[3], v0, v1);
                MMAH(o[2*tp+1], pa[0], pa[1], pa[2], pa[3], v2, v3);
            }
        }
    }

    // ---- normalize + single fp16 store ----
    const float inv0 = 1.0f / l0;
    const float inv1 = 1.0f / l1;
    const int rowg = q0 + w * 16 + (lane >> 2);
    #pragma unroll
    for (int t = 0; t < 16; t++) {
        size_t g0 = ((size_t)(b * S_LEN + rowg)) * DM + head + t * 8 + (lane & 3) * 2;
        size_t g1 = g0 + 8 * DM;
        *(uint32_t*)(Oh + g0) = pack_h2f(o[t][0] * inv0, o[t][1] * inv0);
        *(uint32_t*)(Oh + g1) = pack_h2f(o[t][2] * inv1, o[t][3] * inv1);
    }
}

// ---------------------------------------------------------------------------
extern "C" void kernel_launch(void* const* d_in, const int* in_sizes, int n_in,
                              void* d_out, int out_size)
{
    const float* x  = (const float*)d_in[0];
    const float* wq = (const float*)d_in[1];
    const float* wk = (const float*)d_in[2];
    const float* wv = (const float*)d_in[3];
    const float* wo = (const float*)d_in[4];
    float* out = (float*)d_out;

    hf *xh, *qh, *kh, *vh, *ah, *wh;
    cudaGetSymbolAddress((void**)&xh, g_xh);
    cudaGetSymbolAddress((void**)&qh, g_qh);
    cudaGetSymbolAddress((void**)&kh, g_kh);
    cudaGetSymbolAddress((void**)&vh, g_vh);
    cudaGetSymbolAddress((void**)&ah, g_ah);
    cudaGetSymbolAddress((void**)&wh, g_wh);
    const size_t WSZ = (size_t)DM * DM;

    convert_x<<<(M_TOT * (size_t)DM) / (256 * 8), 256>>>(x, xh);
    dim3 tgrid(DM / 32, DM / 32, 4), tblk(32, 8);
    transpose_convert4<<<tgrid, tblk>>>(wq, wk, wv, wo, wh);

    cudaFuncSetAttribute(gemm_1t<0>, cudaFuncAttributeMaxDynamicSharedMemorySize,
                         GEMM1_SMEM);
    cudaFuncSetAttribute(gemm_1t<1>, cudaFuncAttributeMaxDynamicSharedMemorySize,
                         GEMM1_SMEM);

    // Fused QKV projection + RoPE epilogue: N = 3*2048, one launch
    dim3 qkvgrid(3 * DM / 128, M_TOT / 128);
    gemm_1t<1><<<qkvgrid, 256, GEMM1_SMEM>>>(xh, wh, qh, kh, vh, nullptr,
                                             M_TOT, DM);

    cudaFuncSetAttribute(flash_tc5, cudaFuncAttributeMaxDynamicSharedMemorySize,
                         FLASH_SMEM_BYTES);
    dim3 fgrid(S_LEN / 128, NH, B_SZ);
    flash_tc5<<<fgrid, 256, FLASH_SMEM_BYTES>>>(qh, kh, vh, ah);

    // Out-proj: fp32 output
    dim3 ogrid(DM / 128, M_TOT / 128);
    gemm_1t<0><<<ogrid, 256, GEMM1_SMEM>>>(ah, wh + 3 * WSZ, nullptr, nullptr,
                                           nullptr, out, M_TOT, DM);
}